// round 14
// baseline (speedup 1.0000x reference)
#include <cuda_runtime.h>
#include <cuda_fp16.h>
#include <math.h>
#include <stdint.h>

#define NP    65534
#define NTOK  (NP*4)          // 262136 tokens
#define GH    180
#define GW    360
#define NCELL (GH*GW)         // 64800
#define CLN   512

#define SMSB 80               // bytes per smem row (32 fp16 = 64B + 16B pad)
#define CHB  (128*SMSB)       // 10240 bytes per 128x32 fp16 chunk

// ---------------- scratch (device globals: no allocation allowed) ----------------
__device__ __half g_feat[(size_t)NP*96];     // 75 used + zero pad to 96 (fp16)
__device__ int    g_flat[NP];
__device__ __half g_h   [(size_t)NTOK*128];  // transformer state (fp16)
__device__ __half g_qkv [(size_t)NTOK*384];  // fp16 qkv
__device__ float  g_cnt [NCELL];
__device__ __half g_wt  [704512];            // transposed fp16 weights

// ---------------- small PTX helpers ----------------
__device__ __forceinline__ void cpasync16(uint32_t dst, const void* src, bool pred) {
    int sz = pred ? 16 : 0;      // sz=0 => zero-fill 16 bytes
    asm volatile("cp.async.cg.shared.global [%0], [%1], 16, %2;\n"
                 :: "r"(dst), "l"(src), "r"(sz));
}
__device__ __forceinline__ void cp_commit() {
    asm volatile("cp.async.commit_group;\n" ::);
}
__device__ __forceinline__ void ldm4(uint32_t& r0, uint32_t& r1, uint32_t& r2, uint32_t& r3, uint32_t addr) {
    asm volatile("ldmatrix.sync.aligned.m8n8.x4.shared.b16 {%0,%1,%2,%3}, [%4];\n"
                 : "=r"(r0), "=r"(r1), "=r"(r2), "=r"(r3) : "r"(addr));
}
__device__ __forceinline__ void mma_f16(float* c, const uint32_t* a, uint32_t b0, uint32_t b1) {
    asm volatile("mma.sync.aligned.m16n8k16.row.col.f32.f16.f16.f32 "
                 "{%0,%1,%2,%3}, {%4,%5,%6,%7}, {%8,%9}, {%0,%1,%2,%3};\n"
                 : "+f"(c[0]), "+f"(c[1]), "+f"(c[2]), "+f"(c[3])
                 : "r"(a[0]), "r"(a[1]), "r"(a[2]), "r"(a[3]), "r"(b0), "r"(b1));
}
__device__ __forceinline__ float gelu_t(float u) {
    return 0.5f * u * (1.0f + tanhf(0.7978845608028654f * (u + 0.044715f * u * u * u)));
}
// load 16 fp16 -> float[16] (two 16B vector loads)
__device__ __forceinline__ void ld16h(const __half* p, float* o) {
    uint4 u0 = *(const uint4*)p;
    uint4 u1 = *(const uint4*)(p + 8);
    const uint32_t* w0 = (const uint32_t*)&u0;
    const uint32_t* w1 = (const uint32_t*)&u1;
    #pragma unroll
    for (int i = 0; i < 4; i++) {
        float2 f = __half22float2(*(const __half2*)&w0[i]);
        o[2*i+0] = f.x; o[2*i+1] = f.y;
    }
    #pragma unroll
    for (int i = 0; i < 4; i++) {
        float2 f = __half22float2(*(const __half2*)&w1[i]);
        o[8+2*i+0] = f.x; o[8+2*i+1] = f.y;
    }
}
// dot(q[16], packed 16-fp16 row) — same ascending accumulation order as before
__device__ __forceinline__ float dotp(const float* q, const uint4& a, const uint4& b) {
    const uint32_t* wa = (const uint32_t*)&a;
    const uint32_t* wb = (const uint32_t*)&b;
    float s = 0.0f;
    #pragma unroll
    for (int i = 0; i < 4; i++) {
        float2 f = __half22float2(*(const __half2*)&wa[i]);
        s += q[2*i] * f.x + q[2*i+1] * f.y;
    }
    #pragma unroll
    for (int i = 0; i < 4; i++) {
        float2 f = __half22float2(*(const __half2*)&wb[i]);
        s += q[8+2*i] * f.x + q[9+2*i] * f.y;
    }
    return s;
}
// o[16] += wv * packed 16-fp16 row
__device__ __forceinline__ void accp(float* o, const uint4& a, const uint4& b, float wv) {
    const uint32_t* wa = (const uint32_t*)&a;
    const uint32_t* wb = (const uint32_t*)&b;
    #pragma unroll
    for (int i = 0; i < 4; i++) {
        float2 f = __half22float2(*(const __half2*)&wa[i]);
        o[2*i]   += wv * f.x;
        o[2*i+1] += wv * f.y;
    }
    #pragma unroll
    for (int i = 0; i < 4; i++) {
        float2 f = __half22float2(*(const __half2*)&wb[i]);
        o[8+2*i] += wv * f.x;
        o[9+2*i] += wv * f.y;
    }
}

// 128x128x32 fp16 mma on one k-chunk. aBase/bBase: smem byte addr of 128x32 chunk.
__device__ __forceinline__ void mma_tile16(uint32_t aBase, uint32_t bBase,
                                           int ra0, int rb0, int lk2,
                                           float acc[2][8][4]) {
    #pragma unroll
    for (int kk = 0; kk < 32; kk += 16) {
        uint32_t a[2][4];
        #pragma unroll
        for (int mi = 0; mi < 2; mi++)
            ldm4(a[mi][0], a[mi][1], a[mi][2], a[mi][3],
                 aBase + (uint32_t)((ra0 + mi * 16) * SMSB + (kk + lk2) * 2));
        uint32_t b0[8], b1[8];
        #pragma unroll
        for (int np = 0; np < 4; np++) {
            uint32_t r0, r1, r2, r3;
            ldm4(r0, r1, r2, r3,
                 bBase + (uint32_t)((rb0 + np * 16) * SMSB + (kk + lk2) * 2));
            b0[2*np] = r0; b0[2*np+1] = r1;
            b1[2*np] = r2; b1[2*np+1] = r3;
        }
        #pragma unroll
        for (int mi = 0; mi < 2; mi++)
            #pragma unroll
            for (int ni = 0; ni < 8; ni++)
                mma_f16(acc[mi][ni], a[mi], b0[ni], b1[ni]);
    }
}

// epilogue for 128-row tiles, warp layout 4x2 (warp tile 32x64)
// EPI: 0=bias->C, 1=bias+fp16residual->C, 2=bias+gelu->C, 3=bias+grid-scatter(atomicAdd fp32)
template<int EPI, bool OUT16>
__device__ __forceinline__ void epi12816(float acc[2][8][4], const float* __restrict__ bias,
                                         const void* __restrict__ R, void* __restrict__ C,
                                         int M, int N, int bm, int bn, int wm, int wn, int lane) {
    const int row0 = bm + wm * 32 + (lane >> 2);
    const int col0 = bn + wn * 64 + (lane & 3) * 2;
    #pragma unroll
    for (int mi = 0; mi < 2; mi++) {
        #pragma unroll
        for (int half = 0; half < 2; half++) {
            int gm = row0 + mi * 16 + half * 8;
            if (gm >= M) continue;
            int cell = (EPI == 3) ? g_flat[gm] : 0;
            #pragma unroll
            for (int ni = 0; ni < 8; ni++) {
                int gn = col0 + ni * 8;
                float v0 = acc[mi][ni][half*2 + 0] + bias[gn];
                float v1 = acc[mi][ni][half*2 + 1] + bias[gn + 1];
                if (EPI == 1) {
                    __half2 rh = *(const __half2*)((const __half*)R + (size_t)gm * N + gn);
                    float2 rf = __half22float2(rh);
                    v0 += rf.x; v1 += rf.y;
                }
                if (EPI == 2) { v0 = gelu_t(v0); v1 = gelu_t(v1); }
                if (EPI == 3) {
                    float* dst = (float*)C + (size_t)cell * CLN + gn;
                    atomicAdd(dst,     v0);
                    atomicAdd(dst + 1, v1);
                } else if (OUT16) {
                    *(__half2*)((__half*)C + (size_t)gm * N + gn) = __floats2half2_rn(v0, v1);
                } else {
                    float2 o; o.x = v0; o.y = v1;
                    *(float2*)((float*)C + (size_t)gm * N + gn) = o;
                }
            }
        }
    }
}

// LayerNorm a 128x128 h tile into smem A chunks (fp16), warp w does rows w*16..+15
__device__ __forceinline__ void ln_to_smem(const __half* __restrict__ H, char* smc,
                                           const float* __restrict__ lns,
                                           const float* __restrict__ lnb,
                                           int bm, int M, int w, int lane) {
    const float4 sc4 = ((const float4*)lns)[lane];
    const float4 bc4 = ((const float4*)lnb)[lane];
    #pragma unroll
    for (int rr = 0; rr < 16; rr++) {
        int row = w * 16 + rr;
        int gm  = bm + row;
        float v0 = 0.0f, v1 = 0.0f, v2 = 0.0f, v3 = 0.0f;
        if (gm < M) {
            uint2 u = *(const uint2*)(H + (size_t)gm * 128 + lane * 4);
            float2 fa = __half22float2(*(const __half2*)&u.x);
            float2 fb = __half22float2(*(const __half2*)&u.y);
            v0 = fa.x; v1 = fa.y; v2 = fb.x; v3 = fb.y;
        }
        float sum = v0 + v1 + v2 + v3;
        float sq  = v0*v0 + v1*v1 + v2*v2 + v3*v3;
        #pragma unroll
        for (int o = 16; o > 0; o >>= 1) {
            sum += __shfl_xor_sync(0xffffffffu, sum, o);
            sq  += __shfl_xor_sync(0xffffffffu, sq,  o);
        }
        float mean = sum * (1.0f/128.0f);
        float var  = sq  * (1.0f/128.0f) - mean * mean;
        float r = rsqrtf(var + 1e-5f);
        float o0 = (v0 - mean) * r * sc4.x + bc4.x;
        float o1 = (v1 - mean) * r * sc4.y + bc4.y;
        float o2 = (v2 - mean) * r * sc4.z + bc4.z;
        float o3 = (v3 - mean) * r * sc4.w + bc4.w;
        __half2* d = (__half2*)(smc + (lane >> 3) * CHB + row * SMSB + (lane & 7) * 8);
        d[0] = __floats2half2_rn(o0, o1);
        d[1] = __floats2half2_rn(o2, o3);
    }
}

// ---------------- feature build + grid index + counts (fp16 output) ----------------
__global__ void feat_kernel(const float* __restrict__ x) {
    int i = blockIdx.x * blockDim.x + threadIdx.x;
    if (i >= NP) return;
    const float* xr = x + (size_t)i * 24;
    float lat = xr[0];
    if (lat == -90.0f) lat += 0.0001f;
    float lon = xr[1];
    float t   = xr[2];

    int lati = (int)floorf(90.0f - lat);
    int loni = (int)fmodf(180.0f + floorf(lon + 180.0f), 360.0f);
    int cell = lati * GW + loni;
    g_flat[i] = cell;
    atomicAdd(&g_cnt[cell], 1.0f);

    __half* f = g_feat + (size_t)i * 96;
    f[0] = __float2half_rn(lat * (1.0f/90.0f));
    f[1] = __float2half_rn(lon * (1.0f/180.0f));
    f[2] = __float2half_rn(t   * (1.0f/12.0f));
    #pragma unroll
    for (int j = 3; j < 24; j++) f[j] = __float2half_rn(xr[j]);

    float p0 = -lat - floorf(-lat);
    float p1 =  lon - floorf(lon);
    float p2 =  t + 1.0f;
    f[24] = __float2half_rn(p0); f[25] = __float2half_rn(p1); f[26] = __float2half_rn(p2);
    float p[3] = {p0, p1, p2};
    #pragma unroll
    for (int c = 0; c < 3; c++) {
        float fr = 3.14159274101257324f;
        #pragma unroll
        for (int k = 0; k < 8; k++) {
            float ang = p[c] * fr;
            f[27 + c*8 + k] = __float2half_rn(sinf(ang));
            f[51 + c*8 + k] = __float2half_rn(cosf(ang));
            fr *= 2.0f;
        }
    }
    #pragma unroll
    for (int j = 75; j < 96; j++) f[j] = __float2half_rn(0.0f);
}

// ---------------- all-in-one weight transpose + fp16 round ----------------
__global__ void wconv(const float* __restrict__ W_emb, const float* __restrict__ Wqkv,
                      const float* __restrict__ Wo, const float* __restrict__ Wf1,
                      const float* __restrict__ Wf2, const float* __restrict__ W_comb) {
    int idx = blockIdx.x * blockDim.x + threadIdx.x;
    if (idx >= 704512) return;
    const float* srcs[6] = {W_emb, Wqkv, Wo, Wf1, Wf2, W_comb};
    const int sel [10] = {0,1,1,2,2,3,3,4,4,5};
    const int soff[10] = {0,0,49152,0,16384,0,65536,0,65536,0};
    const int Kt  [10] = {75,128,128,128,128,128,128,512,512,512};
    const int Nt  [10] = {512,384,384,128,128,512,512,128,128,512};
    const int Kp  [10] = {96,128,128,128,128,128,128,512,512,512};
    const int dst [10] = {0,49152,98304,147456,163840,180224,245760,311296,376832,442368};
    int m = 0;
    #pragma unroll
    for (int i = 1; i < 10; i++) if (idx >= dst[i]) m = i;
    int local = idx - dst[m];
    int n = local / Kp[m];
    int k = local - n * Kp[m];
    float v = (k < Kt[m]) ? srcs[sel[m]][soff[m] + (size_t)k * Nt[m] + n] : 0.0f;
    g_wt[idx] = __float2half_rn(v);
}

// ---------------- generic fp16 GEMM, pair-barrier: 2 chunks per wait+sync ----------------
// Ring4 = 2 pair slots; depth-1: issue pair p+1 AFTER sync(p) (its bufs were last read
// by mma pair p-1, which every warp finished before sync(p)).
template<int EPI, bool OUT16>
__global__ void __launch_bounds__(256, 2)
gemm_tc16(const __half* __restrict__ A, const __half* __restrict__ Bt,
          const float* __restrict__ bias, const void* __restrict__ R,
          void* __restrict__ C, int M, int N, int K, int lda, int ldb) {
    extern __shared__ char smc[];
    const int tid  = threadIdx.x;
    const int lane = tid & 31;
    const int w    = tid >> 5;
    const int wm   = w & 3;
    const int wn   = w >> 2;
    const int bm   = blockIdx.y * 128;
    const int bn   = blockIdx.x * 128;

    const uint32_t sA = (uint32_t)__cvta_generic_to_shared(smc);
    const uint32_t sB = sA + 4*CHB;

    float acc[2][8][4];
    #pragma unroll
    for (int mi = 0; mi < 2; mi++)
        #pragma unroll
        for (int ni = 0; ni < 8; ni++)
            #pragma unroll
            for (int r = 0; r < 4; r++) acc[mi][ni][r] = 0.0f;

    const int lrow = (lane & 7) + ((lane >> 3) & 1) * 8;
    const int lk2  = ((lane >> 4) & 1) * 8;
    const int ra0  = wm * 32 + lrow;
    const int rb0  = wn * 64 + lrow;
    const int nc   = K >> 5;
    const int npair = (nc + 1) >> 1;

    auto load_chunk = [&](int c) {
        int buf = c & 3;
        int k0  = c * 32;
        #pragma unroll
        for (int l = 0; l < 2; l++) {
            int idx = tid + l * 256;      // 0..511
            int row = idx >> 2;
            int g   = idx & 3;
            bool pa = (bm + row) < M;
            const void* src = pa ? (const void*)(A + (size_t)(bm + row) * lda + k0 + g * 8)
                                 : (const void*)A;
            cpasync16(sA + (uint32_t)(buf*CHB + row*SMSB + g*16), src, pa);
        }
        #pragma unroll
        for (int l = 0; l < 2; l++) {
            int idx = tid + l * 256;
            int row = idx >> 2;
            int g   = idx & 3;
            cpasync16(sB + (uint32_t)(buf*CHB + row*SMSB + g*16),
                      Bt + (size_t)(bn + row) * ldb + k0 + g * 8, true);
        }
    };
    auto load_pair = [&](int p) {
        load_chunk(2*p);
        if (2*p + 1 < nc) load_chunk(2*p + 1);
        cp_commit();
    };

    load_pair(0);
    for (int p = 0; p < npair; p++) {
        asm volatile("cp.async.wait_group 0;\n" ::);
        __syncthreads();                          // publish pair p; fence ring reuse
        if (p + 1 < npair) load_pair(p + 1);
        int c0 = 2*p;
        mma_tile16(sA + (uint32_t)((c0 & 3)*CHB), sB + (uint32_t)((c0 & 3)*CHB),
                   ra0, rb0, lk2, acc);
        if (c0 + 1 < nc)
            mma_tile16(sA + (uint32_t)(((c0+1) & 3)*CHB), sB + (uint32_t)(((c0+1) & 3)*CHB),
                       ra0, rb0, lk2, acc);
    }
    epi12816<EPI, OUT16>(acc, bias, R, C, M, N, bm, bn, wm, wn, lane);
}

// ---------------- fused LN + QKV GEMM (A resident fp16): K=128, N=384 ----------------
// Pair-barrier B stream over 12 chunks (6 pairs).
__global__ void __launch_bounds__(256, 2)
lnA16(const __half* __restrict__ H, const __half* __restrict__ Bt,
      const float* __restrict__ bias, const float* __restrict__ lns,
      const float* __restrict__ lnb, void* __restrict__ C, int M, int N) {
    extern __shared__ char smc[];
    const int tid  = threadIdx.x;
    const int lane = tid & 31;
    const int w    = tid >> 5;
    const int bm   = blockIdx.y * 128;

    const uint32_t sA = (uint32_t)__cvta_generic_to_shared(smc);
    const uint32_t sB = sA + 4*CHB;

    auto loadB = [&](int s) {
        int nb = s >> 2, kc = s & 3, buf = s & 3;
        #pragma unroll
        for (int l = 0; l < 2; l++) {
            int idx = tid + l * 256;
            int row = idx >> 2;
            int g   = idx & 3;
            cpasync16(sB + (uint32_t)(buf*CHB + row*SMSB + g*16),
                      Bt + (size_t)(nb * 128 + row) * 128 + kc * 32 + g * 8, true);
        }
    };
    auto loadBpair = [&](int p) {
        loadB(2*p);
        loadB(2*p + 1);
        cp_commit();
    };

    loadBpair(0);

    ln_to_smem(H, smc, lns, lnb, bm, M, w, lane);

    const int lrow = (lane & 7) + ((lane >> 3) & 1) * 8;
    const int lk2  = ((lane >> 4) & 1) * 8;
    const int ra0  = (w & 3) * 32 + lrow;
    const int rb0  = (w >> 2) * 64 + lrow;

    float acc[2][8][4];
    const int nst = (N >> 7) * 4;      // 12
    const int npair = nst >> 1;        // 6
    for (int p = 0; p < npair; p++) {
        asm volatile("cp.async.wait_group 0;\n" ::);
        __syncthreads();               // publish pair p (and LN tile at p=0)
        if (p + 1 < npair) loadBpair(p + 1);
        #pragma unroll
        for (int sub = 0; sub < 2; sub++) {
            int s = 2*p + sub;
            if ((s & 3) == 0) {
                #pragma unroll
                for (int mi = 0; mi < 2; mi++)
                    #pragma unroll
                    for (int ni = 0; ni < 8; ni++)
                        #pragma unroll
                        for (int r = 0; r < 4; r++) acc[mi][ni][r] = 0.0f;
            }
            mma_tile16(sA + (uint32_t)((s & 3)*CHB), sB + (uint32_t)((s & 3)*CHB),
                       ra0, rb0, lk2, acc);
            if ((s & 3) == 3)
                epi12816<0, true>(acc, bias, nullptr, C, M, N, bm, (s >> 2) * 128,
                                  w & 3, w >> 2, lane);
        }
    }
}

// ---------------- fused LN2 + FF1 + GELU + FF2 + residual: all in one CTA ----------------
// smem: A[4ch]=40K | G[4ch]=40K | B1[4ch]=40K | B2[2][4ch]=80K  = 200KB -> occ 1
__global__ void __launch_bounds__(256, 1)
ffn16(__half* __restrict__ H, const __half* __restrict__ B1t,
      const __half* __restrict__ B2t, const float* __restrict__ bf1,
      const float* __restrict__ bf2, const float* __restrict__ lns,
      const float* __restrict__ lnb, int M) {
    extern __shared__ char smc[];
    const int tid  = threadIdx.x;
    const int lane = tid & 31;
    const int w    = tid >> 5;
    const int wm   = w & 3;
    const int wn   = w >> 2;
    const int bm   = blockIdx.y * 128;

    const uint32_t sA  = (uint32_t)__cvta_generic_to_shared(smc);
    const uint32_t sG  = sA + 4*CHB;
    const uint32_t sB1 = sA + 8*CHB;
    const uint32_t sB2 = sA + 12*CHB;
    char* smG = smc + 4*CHB;

    auto loadB1 = [&](int nb) {
        #pragma unroll
        for (int kc = 0; kc < 4; kc++) {
            #pragma unroll
            for (int l = 0; l < 2; l++) {
                int idx = tid + l * 256;
                int row = idx >> 2;
                int g   = idx & 3;
                cpasync16(sB1 + (uint32_t)(kc*CHB + row*SMSB + g*16),
                          B1t + (size_t)(nb * 128 + row) * 128 + kc * 32 + g * 8, true);
            }
        }
        cp_commit();
    };
    auto loadB2 = [&](int nb, int buf) {
        #pragma unroll
        for (int kc = 0; kc < 4; kc++) {
            #pragma unroll
            for (int l = 0; l < 2; l++) {
                int idx = tid + l * 256;
                int row = idx >> 2;
                int g   = idx & 3;
                cpasync16(sB2 + (uint32_t)(buf*4*CHB + kc*CHB + row*SMSB + g*16),
                          B2t + (size_t)row * 512 + nb * 128 + kc * 32 + g * 8, true);
            }
        }
        cp_commit();
    };

    loadB1(0);
    loadB2(0, 0);

    ln_to_smem(H, smc, lns, lnb, bm, M, w, lane);

    asm volatile("cp.async.wait_group 0;\n" ::);
    __syncthreads();    // B1[0], B2[0], LN tile all published

    const int lrow = (lane & 7) + ((lane >> 3) & 1) * 8;
    const int lk2  = ((lane >> 4) & 1) * 8;
    const int ra0  = wm * 32 + lrow;
    const int rb0  = wn * 64 + lrow;

    float acc2[2][8][4];
    #pragma unroll
    for (int mi = 0; mi < 2; mi++)
        #pragma unroll
        for (int ni = 0; ni < 8; ni++)
            #pragma unroll
            for (int r = 0; r < 4; r++) acc2[mi][ni][r] = 0.0f;

    for (int nb = 0; nb < 4; nb++) {
        if (nb > 0) {
            asm volatile("cp.async.wait_group 0;\n" ::);
            __syncthreads();   // publish B1[nb], B2[nb&1]; FF2[nb-1] done -> G writable
        }
        // FF1: A x B1[nb] -> acc1 (full 128x128 tile, 4 k-chunks)
        float acc1[2][8][4];
        #pragma unroll
        for (int mi = 0; mi < 2; mi++)
            #pragma unroll
            for (int ni = 0; ni < 8; ni++)
                #pragma unroll
                for (int r = 0; r < 4; r++) acc1[mi][ni][r] = 0.0f;
        #pragma unroll
        for (int kc = 0; kc < 4; kc++)
            mma_tile16(sA + (uint32_t)(kc*CHB), sB1 + (uint32_t)(kc*CHB),
                       ra0, rb0, lk2, acc1);

        // gelu + bias -> G smem
        {
            const int r0 = wm * 32 + (lane >> 2);
            const int c0 = wn * 64 + (lane & 3) * 2;
            #pragma unroll
            for (int mi = 0; mi < 2; mi++) {
                #pragma unroll
                for (int half = 0; half < 2; half++) {
                    int row = r0 + mi * 16 + half * 8;
                    #pragma unroll
                    for (int ni = 0; ni < 8; ni++) {
                        int col = c0 + ni * 8;
                        float v0 = gelu_t(acc1[mi][ni][half*2 + 0] + bf1[nb * 128 + col]);
                        float v1 = gelu_t(acc1[mi][ni][half*2 + 1] + bf1[nb * 128 + col + 1]);
                        *(__half2*)(smG + ((col >> 5) * CHB) + row * SMSB + (col & 31) * 2)
                            = __floats2half2_rn(v0, v1);
                    }
                }
            }
        }
        __syncthreads();   // publish G; all warps done with B1[nb]

        if (nb < 3) {
            loadB1(nb + 1);
            loadB2(nb + 1, (nb + 1) & 1);
        }

        // FF2: G x B2[nb&1] -> acc2 accumulate
        #pragma unroll
        for (int kc = 0; kc < 4; kc++)
            mma_tile16(sG + (uint32_t)(kc*CHB),
                       sB2 + (uint32_t)((nb & 1)*4*CHB + kc*CHB),
                       ra0, rb0, lk2, acc2);
    }

    epi12816<1, true>(acc2, bf2, H, H, M, 128, bm, 0, wm, wn, lane);
}

// ---------------- fused attention + o-proj (+fp16 residual): N=128, K=128 ----------------
// K/V hoisted: loaded once per (point,head), re-used for all 4 query tokens.
__global__ void __launch_bounds__(256, 2)
attn16(const __half* __restrict__ qkv, const __half* __restrict__ Bt,
       const float* __restrict__ bias, __half* __restrict__ H, int M) {
    extern __shared__ char smc[];
    const int tid  = threadIdx.x;
    const int lane = tid & 31;
    const int w    = tid >> 5;
    const int bm   = blockIdx.y * 128;

    const uint32_t sA = (uint32_t)__cvta_generic_to_shared(smc);
    const uint32_t sB = sA + 4*CHB;

    // all 4 B chunks up front (one commit)
    #pragma unroll
    for (int kc = 0; kc < 4; kc++) {
        #pragma unroll
        for (int l = 0; l < 2; l++) {
            int idx = tid + l * 256;
            int row = idx >> 2;
            int g   = idx & 3;
            cpasync16(sB + (uint32_t)(kc*CHB + row*SMSB + g*16),
                      Bt + (size_t)row * 128 + kc * 32 + g * 8, true);
        }
    }
    cp_commit();

    // attention
    {
        int p_local = tid >> 3;
        int hh = tid & 7;
        int p = (bm >> 2) + p_local;
        if (p < NP) {
            const __half* base = qkv + (size_t)p * 1536 + hh * 16;
            // hoist K, V (4 rows x 16 fp16 each, packed)
            uint4 K0[4], K1[4], V0[4], V1[4];
            #pragma unroll
            for (int ki = 0; ki < 4; ki++) {
                K0[ki] = *(const uint4*)(base + 128 + ki * 384);
                K1[ki] = *(const uint4*)(base + 128 + ki * 384 + 8);
                V0[ki] = *(const uint4*)(base + 256 + ki * 384);
                V1[ki] = *(const uint4*)(base + 256 + ki * 384 + 8);
            }
            #pragma unroll
            for (int qi = 0; qi < 4; qi++) {
                float q[16];
                ld16h(base + qi * 384, q);
                float sc[4];
                float mx = -1e30f;
                #pragma unroll
                for (int ki = 0; ki < 4; ki++) {
                    float s = dotp(q, K0[ki], K1[ki]) * 0.25f;
                    sc[ki] = s;
                    mx = fmaxf(mx, s);
                }
                float sum = 0.0f;
                #pragma unroll
                for (int ki = 0; ki < 4; ki++) { sc[ki] = expf(sc[ki] - mx); sum += sc[ki]; }
                float inv = 1.0f / sum;
                float acco[16];
                #pragma unroll
                for (int d = 0; d < 16; d++) acco[d] = 0.0f;
                #pragma unroll
                for (int ki = 0; ki < 4; ki++)
                    accp(acco, V0[ki], V1[ki], sc[ki] * inv);
                int row = p_local * 4 + qi;
                __half2* d = (__half2*)(smc + (hh >> 1) * CHB + row * SMSB + (hh & 1) * 32);
                #pragma unroll
                for (int c = 0; c < 8; c++)
                    d[c] = __floats2half2_rn(acco[2*c], acco[2*c+1]);
            }
        } else {
            int p_l = tid >> 3, hh2 = tid & 7;
            #pragma unroll
            for (int qi = 0; qi < 4; qi++) {
                int row = p_l * 4 + qi;
                __half2* d = (__half2*)(smc + (hh2 >> 1) * CHB + row * SMSB + (hh2 & 1) * 32);
                #pragma unroll
                for (int c = 0; c < 8; c++) d[c] = __floats2half2_rn(0.0f, 0.0f);
            }
        }
    }

    asm volatile("cp.async.wait_group 0;\n" ::);
    __syncthreads();

    float acc[2][8][4];
    #pragma unroll
    for (int mi = 0; mi < 2; mi++)
        #pragma unroll
        for (int ni = 0; ni < 8; ni++)
            #pragma unroll
            for (int r = 0; r < 4; r++) acc[mi][ni][r] = 0.0f;

    const int lrow = (lane & 7) + ((lane >> 3) & 1) * 8;
    const int lk2  = ((lane >> 4) & 1) * 8;
    const int ra0  = (w & 3) * 32 + lrow;
    const int rb0  = (w >> 2) * 64 + lrow;

    #pragma unroll
    for (int kc = 0; kc < 4; kc++)
        mma_tile16(sA + (uint32_t)(kc*CHB), sB + (uint32_t)(kc*CHB),
                   ra0, rb0, lk2, acc);
    epi12816<1, true>(acc, bias, H, H, M, 128, bm, 0, w & 3, w >> 2, lane);
}

// ---------------- output init + final divide (vectorized) ----------------
__global__ void zero_kernel(float4* __restrict__ out) {
    int i = blockIdx.x * blockDim.x + threadIdx.x;
    int n4 = NCELL * CLN / 4;
    if (i < n4) out[i] = make_float4(0.f, 0.f, 0.f, 0.f);
    else if (i < n4 + NCELL) g_cnt[i - n4] = 0.0f;
}

__global__ void div_kernel(float4* __restrict__ out) {
    int i = blockIdx.x * blockDim.x + threadIdx.x;
    if (i >= NCELL * CLN / 4) return;
    float inv = 1.0f / fmaxf(g_cnt[i >> 7], 1.0f);
    float4 v = out[i];
    v.x *= inv; v.y *= inv; v.z *= inv; v.w *= inv;
    out[i] = v;
}

// ---------------- driver ----------------
extern "C" void kernel_launch(void* const* d_in, const int* in_sizes, int n_in,
                              void* d_out, int out_size) {
    const float* x      = (const float*)d_in[0];
    const float* W_emb  = (const float*)d_in[1];
    const float* b_emb  = (const float*)d_in[2];
    const float* ln1_s  = (const float*)d_in[3];
    const float* ln1_b  = (const float*)d_in[4];
    const float* Wqkv   = (const float*)d_in[5];
    const float* bqkv   = (const float*)d_in[6];
    const float* Wo     = (const float*)d_in[7];
    const float* bo     = (const float*)d_in[8];
    const float* ln2_s  = (const float*)d_in[9];
    const float* ln2_b  = (const float*)d_in[10];
    const float* Wf1    = (const float*)d_in[11];
    const float* bf1    = (const float*)d_in[12];
    const float* Wf2    = (const float*)d_in[13];
    const float* bf2    = (const float*)d_in[14];
    const float* W_comb = (const float*)d_in[15];
    const float* b_comb = (const float*)d_in[16];
    float* out = (float*)d_out;

    __half *p_feat, *p_h, *p_qkv, *p_wt;
    cudaGetSymbolAddress((void**)&p_feat, g_feat);
    cudaGetSymbolAddress((void**)&p_h,    g_h);
    cudaGetSymbolAddress((void**)&p_qkv,  g_qkv);
    cudaGetSymbolAddress((void**)&p_wt,   g_wt);

    const int SMEM   = 8 * CHB;    // 81920
    const int SMEM_F = 20 * CHB;   // 204800
    static bool attr_done = false;
    if (!attr_done) {
        cudaFuncSetAttribute((const void*)gemm_tc16<0,true>,  cudaFuncAttributeMaxDynamicSharedMemorySize, SMEM);
        cudaFuncSetAttribute((const void*)gemm_tc16<3,false>, cudaFuncAttributeMaxDynamicSharedMemorySize, SMEM);
        cudaFuncSetAttribute((const void*)lnA16,  cudaFuncAttributeMaxDynamicSharedMemorySize, SMEM);
        cudaFuncSetAttribute((const void*)attn16, cudaFuncAttributeMaxDynamicSharedMemorySize, SMEM);
        cudaFuncSetAttribute((const void*)ffn16,  cudaFuncAttributeMaxDynamicSharedMemorySize, SMEM_F);
        attr_done = true;
    }

    const int TB = 256;

    // fp16 weight offsets in g_wt
    __half* wembT  = p_wt + 0;        // [512][96]
    __half* wqkvT0 = p_wt + 49152;    // [384][128]
    __half* wqkvT1 = p_wt + 98304;
    __half* woT0   = p_wt + 147456;   // [128][128]
    __half* woT1   = p_wt + 163840;
    __half* wf1T0  = p_wt + 180224;   // [512][128]
    __half* wf1T1  = p_wt + 245760;
    __half* wf2T0  = p_wt + 311296;   // [128][512]
    __half* wf2T1  = p_wt + 376832;
    __half* wcombT = p_wt + 442368;   // [512][512]

    wconv<<<(704512 + TB - 1) / TB, TB>>>(W_emb, Wqkv, Wo, Wf1, Wf2, W_comb);
    // zero out + counts BEFORE feat (feat accumulates counts)
    zero_kernel<<<(NCELL * CLN / 4 + NCELL + TB - 1) / TB, TB>>>((float4*)out);
    feat_kernel<<<(NP + TB - 1) / TB, TB>>>(x);

    // embedding: feat(NP x 96 fp16) @ W_emb -> h (fp16)
    gemm_tc16<0,true><<<dim3(4, (NP + 127) / 128), TB, SMEM>>>(
        p_feat, wembT, b_emb, nullptr, p_h, NP, 512, 96, 96, 96);

    const __half* wqkvT[2] = {wqkvT0, wqkvT1};
    const __half* woT[2]   = {woT0, woT1};
    const __half* wf1T[2]  = {wf1T0, wf1T1};
    const __half* wf2T[2]  = {wf2T0, wf2T1};
    const int MB = (NTOK + 127) / 128;   // 2048

    for (int i = 0; i < 2; i++) {
        lnA16<<<dim3(1, MB), TB, SMEM>>>(p_h, wqkvT[i], bqkv + i * 384,
                                         ln1_s + i * 128, ln1_b + i * 128,
                                         p_qkv, NTOK, 384);
        attn16<<<dim3(1, MB), TB, SMEM>>>(p_qkv, woT[i], bo + i * 128, p_h, NTOK);
        ffn16<<<dim3(1, MB), TB, SMEM_F>>>(p_h, wf1T[i], wf2T[i],
                                           bf1 + i * 512, bf2 + i * 128,
                                           ln2_s + i * 128, ln2_b + i * 128, NTOK);
    }

    // head: h(NP x 512 fp16) @ W_comb -> scattered directly into out (atomicAdd)
    gemm_tc16<3,false><<<dim3(4, (NP + 127) / 128), TB, SMEM>>>(
        p_h, wcombT, b_comb, nullptr, out, NP, 512, 512, 512, 512);

    // final divide by counts
    div_kernel<<<(NCELL * CLN / 4 + TB - 1) / TB, TB>>>((float4*)out);
}

// round 15
// speedup vs baseline: 1.5056x; 1.5056x over previous
#include <cuda_runtime.h>
#include <cuda_fp16.h>
#include <math.h>
#include <stdint.h>

#define NP    65534
#define NTOK  (NP*4)          // 262136 tokens
#define GH    180
#define GW    360
#define NCELL (GH*GW)         // 64800
#define CLN   512

#define SMSB 80               // bytes per smem row (32 fp16 = 64B + 16B pad)
#define CHB  (128*SMSB)       // 10240 bytes per 128x32 fp16 chunk

// ---------------- scratch (device globals: no allocation allowed) ----------------
__device__ __half g_feat[(size_t)NP*96];     // 75 used + zero pad to 96 (fp16)
__device__ int    g_flat[NP];
__device__ __half g_h   [(size_t)NTOK*128];  // transformer state (fp16)
__device__ __half g_qkv [(size_t)NTOK*384];  // fp16 qkv
__device__ float  g_cnt [NCELL];
__device__ __half g_wt  [704512];            // transposed fp16 weights

// ---------------- small PTX helpers ----------------
__device__ __forceinline__ void cpasync16(uint32_t dst, const void* src, bool pred) {
    int sz = pred ? 16 : 0;      // sz=0 => zero-fill 16 bytes
    asm volatile("cp.async.cg.shared.global [%0], [%1], 16, %2;\n"
                 :: "r"(dst), "l"(src), "r"(sz));
}
__device__ __forceinline__ void cp_commit() {
    asm volatile("cp.async.commit_group;\n" ::);
}
__device__ __forceinline__ void ldm4(uint32_t& r0, uint32_t& r1, uint32_t& r2, uint32_t& r3, uint32_t addr) {
    asm volatile("ldmatrix.sync.aligned.m8n8.x4.shared.b16 {%0,%1,%2,%3}, [%4];\n"
                 : "=r"(r0), "=r"(r1), "=r"(r2), "=r"(r3) : "r"(addr));
}
__device__ __forceinline__ void mma_f16(float* c, const uint32_t* a, uint32_t b0, uint32_t b1) {
    asm volatile("mma.sync.aligned.m16n8k16.row.col.f32.f16.f16.f32 "
                 "{%0,%1,%2,%3}, {%4,%5,%6,%7}, {%8,%9}, {%0,%1,%2,%3};\n"
                 : "+f"(c[0]), "+f"(c[1]), "+f"(c[2]), "+f"(c[3])
                 : "r"(a[0]), "r"(a[1]), "r"(a[2]), "r"(a[3]), "r"(b0), "r"(b1));
}
__device__ __forceinline__ float gelu_t(float u) {
    return 0.5f * u * (1.0f + tanhf(0.7978845608028654f * (u + 0.044715f * u * u * u)));
}
// load 16 fp16 -> float[16] (two 16B vector loads)
__device__ __forceinline__ void ld16h(const __half* p, float* o) {
    uint4 u0 = *(const uint4*)p;
    uint4 u1 = *(const uint4*)(p + 8);
    const uint32_t* w0 = (const uint32_t*)&u0;
    const uint32_t* w1 = (const uint32_t*)&u1;
    #pragma unroll
    for (int i = 0; i < 4; i++) {
        float2 f = __half22float2(*(const __half2*)&w0[i]);
        o[2*i+0] = f.x; o[2*i+1] = f.y;
    }
    #pragma unroll
    for (int i = 0; i < 4; i++) {
        float2 f = __half22float2(*(const __half2*)&w1[i]);
        o[8+2*i+0] = f.x; o[8+2*i+1] = f.y;
    }
}
// dot(q[16], packed 16-fp16 row)
__device__ __forceinline__ float dotp(const float* q, const uint4& a, const uint4& b) {
    const uint32_t* wa = (const uint32_t*)&a;
    const uint32_t* wb = (const uint32_t*)&b;
    float s = 0.0f;
    #pragma unroll
    for (int i = 0; i < 4; i++) {
        float2 f = __half22float2(*(const __half2*)&wa[i]);
        s += q[2*i] * f.x + q[2*i+1] * f.y;
    }
    #pragma unroll
    for (int i = 0; i < 4; i++) {
        float2 f = __half22float2(*(const __half2*)&wb[i]);
        s += q[8+2*i] * f.x + q[9+2*i] * f.y;
    }
    return s;
}
// o[16] += wv * packed 16-fp16 row
__device__ __forceinline__ void accp(float* o, const uint4& a, const uint4& b, float wv) {
    const uint32_t* wa = (const uint32_t*)&a;
    const uint32_t* wb = (const uint32_t*)&b;
    #pragma unroll
    for (int i = 0; i < 4; i++) {
        float2 f = __half22float2(*(const __half2*)&wa[i]);
        o[2*i]   += wv * f.x;
        o[2*i+1] += wv * f.y;
    }
    #pragma unroll
    for (int i = 0; i < 4; i++) {
        float2 f = __half22float2(*(const __half2*)&wb[i]);
        o[8+2*i] += wv * f.x;
        o[9+2*i] += wv * f.y;
    }
}

// 128x128x32 fp16 mma on one k-chunk. aBase/bBase: smem byte addr of 128x32 chunk.
__device__ __forceinline__ void mma_tile16(uint32_t aBase, uint32_t bBase,
                                           int ra0, int rb0, int lk2,
                                           float acc[2][8][4]) {
    #pragma unroll
    for (int kk = 0; kk < 32; kk += 16) {
        uint32_t a[2][4];
        #pragma unroll
        for (int mi = 0; mi < 2; mi++)
            ldm4(a[mi][0], a[mi][1], a[mi][2], a[mi][3],
                 aBase + (uint32_t)((ra0 + mi * 16) * SMSB + (kk + lk2) * 2));
        uint32_t b0[8], b1[8];
        #pragma unroll
        for (int np = 0; np < 4; np++) {
            uint32_t r0, r1, r2, r3;
            ldm4(r0, r1, r2, r3,
                 bBase + (uint32_t)((rb0 + np * 16) * SMSB + (kk + lk2) * 2));
            b0[2*np] = r0; b0[2*np+1] = r1;
            b1[2*np] = r2; b1[2*np+1] = r3;
        }
        #pragma unroll
        for (int mi = 0; mi < 2; mi++)
            #pragma unroll
            for (int ni = 0; ni < 8; ni++)
                mma_f16(acc[mi][ni], a[mi], b0[ni], b1[ni]);
    }
}

// epilogue for 128-row tiles, warp layout 4x2 (warp tile 32x64)
// EPI: 0=bias->C, 1=bias+fp16residual->C, 2=bias+gelu->C, 3=bias+grid-scatter(atomicAdd fp32)
template<int EPI, bool OUT16>
__device__ __forceinline__ void epi12816(float acc[2][8][4], const float* __restrict__ bias,
                                         const void* __restrict__ R, void* __restrict__ C,
                                         int M, int N, int bm, int bn, int wm, int wn, int lane) {
    const int row0 = bm + wm * 32 + (lane >> 2);
    const int col0 = bn + wn * 64 + (lane & 3) * 2;
    #pragma unroll
    for (int mi = 0; mi < 2; mi++) {
        #pragma unroll
        for (int half = 0; half < 2; half++) {
            int gm = row0 + mi * 16 + half * 8;
            if (gm >= M) continue;
            int cell = (EPI == 3) ? g_flat[gm] : 0;
            #pragma unroll
            for (int ni = 0; ni < 8; ni++) {
                int gn = col0 + ni * 8;
                float v0 = acc[mi][ni][half*2 + 0] + bias[gn];
                float v1 = acc[mi][ni][half*2 + 1] + bias[gn + 1];
                if (EPI == 1) {
                    __half2 rh = *(const __half2*)((const __half*)R + (size_t)gm * N + gn);
                    float2 rf = __half22float2(rh);
                    v0 += rf.x; v1 += rf.y;
                }
                if (EPI == 2) { v0 = gelu_t(v0); v1 = gelu_t(v1); }
                if (EPI == 3) {
                    float* dst = (float*)C + (size_t)cell * CLN + gn;
                    atomicAdd(dst,     v0);
                    atomicAdd(dst + 1, v1);
                } else if (OUT16) {
                    *(__half2*)((__half*)C + (size_t)gm * N + gn) = __floats2half2_rn(v0, v1);
                } else {
                    float2 o; o.x = v0; o.y = v1;
                    *(float2*)((float*)C + (size_t)gm * N + gn) = o;
                }
            }
        }
    }
}

// LayerNorm a 128x128 h tile into smem A chunks (fp16), warp w does rows w*16..+15
__device__ __forceinline__ void ln_to_smem(const __half* __restrict__ H, char* smc,
                                           const float* __restrict__ lns,
                                           const float* __restrict__ lnb,
                                           int bm, int M, int w, int lane) {
    const float4 sc4 = ((const float4*)lns)[lane];
    const float4 bc4 = ((const float4*)lnb)[lane];
    #pragma unroll
    for (int rr = 0; rr < 16; rr++) {
        int row = w * 16 + rr;
        int gm  = bm + row;
        float v0 = 0.0f, v1 = 0.0f, v2 = 0.0f, v3 = 0.0f;
        if (gm < M) {
            uint2 u = *(const uint2*)(H + (size_t)gm * 128 + lane * 4);
            float2 fa = __half22float2(*(const __half2*)&u.x);
            float2 fb = __half22float2(*(const __half2*)&u.y);
            v0 = fa.x; v1 = fa.y; v2 = fb.x; v3 = fb.y;
        }
        float sum = v0 + v1 + v2 + v3;
        float sq  = v0*v0 + v1*v1 + v2*v2 + v3*v3;
        #pragma unroll
        for (int o = 16; o > 0; o >>= 1) {
            sum += __shfl_xor_sync(0xffffffffu, sum, o);
            sq  += __shfl_xor_sync(0xffffffffu, sq,  o);
        }
        float mean = sum * (1.0f/128.0f);
        float var  = sq  * (1.0f/128.0f) - mean * mean;
        float r = rsqrtf(var + 1e-5f);
        float o0 = (v0 - mean) * r * sc4.x + bc4.x;
        float o1 = (v1 - mean) * r * sc4.y + bc4.y;
        float o2 = (v2 - mean) * r * sc4.z + bc4.z;
        float o3 = (v3 - mean) * r * sc4.w + bc4.w;
        __half2* d = (__half2*)(smc + (lane >> 3) * CHB + row * SMSB + (lane & 7) * 8);
        d[0] = __floats2half2_rn(o0, o1);
        d[1] = __floats2half2_rn(o2, o3);
    }
}

// ---------------- feature build + grid index + counts (fp16 output) ----------------
__global__ void feat_kernel(const float* __restrict__ x) {
    int i = blockIdx.x * blockDim.x + threadIdx.x;
    if (i >= NP) return;
    const float* xr = x + (size_t)i * 24;
    float lat = xr[0];
    if (lat == -90.0f) lat += 0.0001f;
    float lon = xr[1];
    float t   = xr[2];

    int lati = (int)floorf(90.0f - lat);
    int loni = (int)fmodf(180.0f + floorf(lon + 180.0f), 360.0f);
    int cell = lati * GW + loni;
    g_flat[i] = cell;
    atomicAdd(&g_cnt[cell], 1.0f);

    __half* f = g_feat + (size_t)i * 96;
    f[0] = __float2half_rn(lat * (1.0f/90.0f));
    f[1] = __float2half_rn(lon * (1.0f/180.0f));
    f[2] = __float2half_rn(t   * (1.0f/12.0f));
    #pragma unroll
    for (int j = 3; j < 24; j++) f[j] = __float2half_rn(xr[j]);

    float p0 = -lat - floorf(-lat);
    float p1 =  lon - floorf(lon);
    float p2 =  t + 1.0f;
    f[24] = __float2half_rn(p0); f[25] = __float2half_rn(p1); f[26] = __float2half_rn(p2);
    float p[3] = {p0, p1, p2};
    #pragma unroll
    for (int c = 0; c < 3; c++) {
        float fr = 3.14159274101257324f;
        #pragma unroll
        for (int k = 0; k < 8; k++) {
            float ang = p[c] * fr;
            f[27 + c*8 + k] = __float2half_rn(sinf(ang));
            f[51 + c*8 + k] = __float2half_rn(cosf(ang));
            fr *= 2.0f;
        }
    }
    #pragma unroll
    for (int j = 75; j < 96; j++) f[j] = __float2half_rn(0.0f);
}

// ---------------- all-in-one weight transpose + fp16 round ----------------
__global__ void wconv(const float* __restrict__ W_emb, const float* __restrict__ Wqkv,
                      const float* __restrict__ Wo, const float* __restrict__ Wf1,
                      const float* __restrict__ Wf2, const float* __restrict__ W_comb) {
    int idx = blockIdx.x * blockDim.x + threadIdx.x;
    if (idx >= 704512) return;
    const float* srcs[6] = {W_emb, Wqkv, Wo, Wf1, Wf2, W_comb};
    const int sel [10] = {0,1,1,2,2,3,3,4,4,5};
    const int soff[10] = {0,0,49152,0,16384,0,65536,0,65536,0};
    const int Kt  [10] = {75,128,128,128,128,128,128,512,512,512};
    const int Nt  [10] = {512,384,384,128,128,512,512,128,128,512};
    const int Kp  [10] = {96,128,128,128,128,128,128,512,512,512};
    const int dst [10] = {0,49152,98304,147456,163840,180224,245760,311296,376832,442368};
    int m = 0;
    #pragma unroll
    for (int i = 1; i < 10; i++) if (idx >= dst[i]) m = i;
    int local = idx - dst[m];
    int n = local / Kp[m];
    int k = local - n * Kp[m];
    float v = (k < Kt[m]) ? srcs[sel[m]][soff[m] + (size_t)k * Nt[m] + n] : 0.0f;
    g_wt[idx] = __float2half_rn(v);
}

// ---------------- generic fp16 GEMM, R12 scheme: ring-4, depth-2, 1 sync/chunk ----------------
template<int EPI, bool OUT16>
__global__ void __launch_bounds__(256, 2)
gemm_tc16(const __half* __restrict__ A, const __half* __restrict__ Bt,
          const float* __restrict__ bias, const void* __restrict__ R,
          void* __restrict__ C, int M, int N, int K, int lda, int ldb) {
    extern __shared__ char smc[];
    const int tid  = threadIdx.x;
    const int lane = tid & 31;
    const int w    = tid >> 5;
    const int wm   = w & 3;
    const int wn   = w >> 2;
    const int bm   = blockIdx.y * 128;
    const int bn   = blockIdx.x * 128;

    const uint32_t sA = (uint32_t)__cvta_generic_to_shared(smc);
    const uint32_t sB = sA + 4*CHB;

    float acc[2][8][4];
    #pragma unroll
    for (int mi = 0; mi < 2; mi++)
        #pragma unroll
        for (int ni = 0; ni < 8; ni++)
            #pragma unroll
            for (int r = 0; r < 4; r++) acc[mi][ni][r] = 0.0f;

    const int lrow = (lane & 7) + ((lane >> 3) & 1) * 8;
    const int lk2  = ((lane >> 4) & 1) * 8;
    const int ra0  = wm * 32 + lrow;
    const int rb0  = wn * 64 + lrow;
    const int nc   = K >> 5;

    auto load_chunk = [&](int c) {
        int buf = c & 3;
        int k0  = c * 32;
        #pragma unroll
        for (int l = 0; l < 2; l++) {
            int idx = tid + l * 256;      // 0..511
            int row = idx >> 2;
            int g   = idx & 3;
            bool pa = (bm + row) < M;
            const void* src = pa ? (const void*)(A + (size_t)(bm + row) * lda + k0 + g * 8)
                                 : (const void*)A;
            cpasync16(sA + (uint32_t)(buf*CHB + row*SMSB + g*16), src, pa);
        }
        #pragma unroll
        for (int l = 0; l < 2; l++) {
            int idx = tid + l * 256;
            int row = idx >> 2;
            int g   = idx & 3;
            cpasync16(sB + (uint32_t)(buf*CHB + row*SMSB + g*16),
                      Bt + (size_t)(bn + row) * ldb + k0 + g * 8, true);
        }
        cp_commit();
    };

    load_chunk(0);
    if (nc > 1) load_chunk(1);
    for (int c = 0; c < nc; c++) {
        if (c + 2 < nc) {
            load_chunk(c + 2);
            asm volatile("cp.async.wait_group 2;\n" ::);
        } else if (c + 1 < nc) {
            asm volatile("cp.async.wait_group 1;\n" ::);
        } else {
            asm volatile("cp.async.wait_group 0;\n" ::);
        }
        __syncthreads();                          // publish chunk c + fence ring reuse
        int buf = c & 3;
        mma_tile16(sA + (uint32_t)(buf*CHB), sB + (uint32_t)(buf*CHB), ra0, rb0, lk2, acc);
    }
    epi12816<EPI, OUT16>(acc, bias, R, C, M, N, bm, bn, wm, wn, lane);
}

// ---------------- fused LN + QKV GEMM (A resident fp16): K=128, N=384 ----------------
// R12 scheme: B ring-4, depth-2, 1 sync/chunk.
__global__ void __launch_bounds__(256, 2)
lnA16(const __half* __restrict__ H, const __half* __restrict__ Bt,
      const float* __restrict__ bias, const float* __restrict__ lns,
      const float* __restrict__ lnb, void* __restrict__ C, int M, int N) {
    extern __shared__ char smc[];
    const int tid  = threadIdx.x;
    const int lane = tid & 31;
    const int w    = tid >> 5;
    const int bm   = blockIdx.y * 128;

    const uint32_t sA = (uint32_t)__cvta_generic_to_shared(smc);
    const uint32_t sB = sA + 4*CHB;

    auto loadB = [&](int s) {
        int nb = s >> 2, kc = s & 3, buf = s & 3;
        #pragma unroll
        for (int l = 0; l < 2; l++) {
            int idx = tid + l * 256;
            int row = idx >> 2;
            int g   = idx & 3;
            cpasync16(sB + (uint32_t)(buf*CHB + row*SMSB + g*16),
                      Bt + (size_t)(nb * 128 + row) * 128 + kc * 32 + g * 8, true);
        }
        cp_commit();
    };

    loadB(0);
    loadB(1);

    ln_to_smem(H, smc, lns, lnb, bm, M, w, lane);

    const int lrow = (lane & 7) + ((lane >> 3) & 1) * 8;
    const int lk2  = ((lane >> 4) & 1) * 8;
    const int ra0  = (w & 3) * 32 + lrow;
    const int rb0  = (w >> 2) * 64 + lrow;

    float acc[2][8][4];
    const int nst = (N >> 7) * 4;
    for (int s = 0; s < nst; s++) {
        if (s + 2 < nst) {
            loadB(s + 2);
            asm volatile("cp.async.wait_group 2;\n" ::);
        } else if (s + 1 < nst) {
            asm volatile("cp.async.wait_group 1;\n" ::);
        } else {
            asm volatile("cp.async.wait_group 0;\n" ::);
        }
        __syncthreads();                  // publish B chunk s (and LN tile at s=0)
        if ((s & 3) == 0) {
            #pragma unroll
            for (int mi = 0; mi < 2; mi++)
                #pragma unroll
                for (int ni = 0; ni < 8; ni++)
                    #pragma unroll
                    for (int r = 0; r < 4; r++) acc[mi][ni][r] = 0.0f;
        }
        mma_tile16(sA + (uint32_t)((s & 3)*CHB), sB + (uint32_t)((s & 3)*CHB),
                   ra0, rb0, lk2, acc);
        if ((s & 3) == 3)
            epi12816<0, true>(acc, bias, nullptr, C, M, N, bm, (s >> 2) * 128,
                              w & 3, w >> 2, lane);
    }
}

// ---------------- fused LN2 + FF1 + GELU + FF2 + residual: all in one CTA ----------------
// smem: A[4ch]=40K | G[4ch]=40K | B1[4ch]=40K | B2[2][4ch]=80K  = 200KB -> occ 1
__global__ void __launch_bounds__(256, 1)
ffn16(__half* __restrict__ H, const __half* __restrict__ B1t,
      const __half* __restrict__ B2t, const float* __restrict__ bf1,
      const float* __restrict__ bf2, const float* __restrict__ lns,
      const float* __restrict__ lnb, int M) {
    extern __shared__ char smc[];
    const int tid  = threadIdx.x;
    const int lane = tid & 31;
    const int w    = tid >> 5;
    const int wm   = w & 3;
    const int wn   = w >> 2;
    const int bm   = blockIdx.y * 128;

    const uint32_t sA  = (uint32_t)__cvta_generic_to_shared(smc);
    const uint32_t sG  = sA + 4*CHB;
    const uint32_t sB1 = sA + 8*CHB;
    const uint32_t sB2 = sA + 12*CHB;
    char* smG = smc + 4*CHB;

    auto loadB1 = [&](int nb) {
        #pragma unroll
        for (int kc = 0; kc < 4; kc++) {
            #pragma unroll
            for (int l = 0; l < 2; l++) {
                int idx = tid + l * 256;
                int row = idx >> 2;
                int g   = idx & 3;
                cpasync16(sB1 + (uint32_t)(kc*CHB + row*SMSB + g*16),
                          B1t + (size_t)(nb * 128 + row) * 128 + kc * 32 + g * 8, true);
            }
        }
        cp_commit();
    };
    auto loadB2 = [&](int nb, int buf) {
        #pragma unroll
        for (int kc = 0; kc < 4; kc++) {
            #pragma unroll
            for (int l = 0; l < 2; l++) {
                int idx = tid + l * 256;
                int row = idx >> 2;
                int g   = idx & 3;
                cpasync16(sB2 + (uint32_t)(buf*4*CHB + kc*CHB + row*SMSB + g*16),
                          B2t + (size_t)row * 512 + nb * 128 + kc * 32 + g * 8, true);
            }
        }
        cp_commit();
    };

    loadB1(0);
    loadB2(0, 0);

    ln_to_smem(H, smc, lns, lnb, bm, M, w, lane);

    asm volatile("cp.async.wait_group 0;\n" ::);
    __syncthreads();    // B1[0], B2[0], LN tile all published

    const int lrow = (lane & 7) + ((lane >> 3) & 1) * 8;
    const int lk2  = ((lane >> 4) & 1) * 8;
    const int ra0  = wm * 32 + lrow;
    const int rb0  = wn * 64 + lrow;

    float acc2[2][8][4];
    #pragma unroll
    for (int mi = 0; mi < 2; mi++)
        #pragma unroll
        for (int ni = 0; ni < 8; ni++)
            #pragma unroll
            for (int r = 0; r < 4; r++) acc2[mi][ni][r] = 0.0f;

    for (int nb = 0; nb < 4; nb++) {
        if (nb > 0) {
            asm volatile("cp.async.wait_group 0;\n" ::);
            __syncthreads();   // publish B1[nb], B2[nb&1]; FF2[nb-1] done -> G writable
        }
        // FF1: A x B1[nb] -> acc1 (full 128x128 tile, 4 k-chunks)
        float acc1[2][8][4];
        #pragma unroll
        for (int mi = 0; mi < 2; mi++)
            #pragma unroll
            for (int ni = 0; ni < 8; ni++)
                #pragma unroll
                for (int r = 0; r < 4; r++) acc1[mi][ni][r] = 0.0f;
        #pragma unroll
        for (int kc = 0; kc < 4; kc++)
            mma_tile16(sA + (uint32_t)(kc*CHB), sB1 + (uint32_t)(kc*CHB),
                       ra0, rb0, lk2, acc1);

        // gelu + bias -> G smem
        {
            const int r0 = wm * 32 + (lane >> 2);
            const int c0 = wn * 64 + (lane & 3) * 2;
            #pragma unroll
            for (int mi = 0; mi < 2; mi++) {
                #pragma unroll
                for (int half = 0; half < 2; half++) {
                    int row = r0 + mi * 16 + half * 8;
                    #pragma unroll
                    for (int ni = 0; ni < 8; ni++) {
                        int col = c0 + ni * 8;
                        float v0 = gelu_t(acc1[mi][ni][half*2 + 0] + bf1[nb * 128 + col]);
                        float v1 = gelu_t(acc1[mi][ni][half*2 + 1] + bf1[nb * 128 + col + 1]);
                        *(__half2*)(smG + ((col >> 5) * CHB) + row * SMSB + (col & 31) * 2)
                            = __floats2half2_rn(v0, v1);
                    }
                }
            }
        }
        __syncthreads();   // publish G; all warps done with B1[nb]

        if (nb < 3) {
            loadB1(nb + 1);
            loadB2(nb + 1, (nb + 1) & 1);
        }

        // FF2: G x B2[nb&1] -> acc2 accumulate
        #pragma unroll
        for (int kc = 0; kc < 4; kc++)
            mma_tile16(sG + (uint32_t)(kc*CHB),
                       sB2 + (uint32_t)((nb & 1)*4*CHB + kc*CHB),
                       ra0, rb0, lk2, acc2);
    }

    epi12816<1, true>(acc2, bf2, H, H, M, 128, bm, 0, wm, wn, lane);
}

// ---------------- fused attention + o-proj (+fp16 residual): N=128, K=128 ----------------
// K/V hoisted: loaded once per (point,head), re-used for all 4 query tokens.
__global__ void __launch_bounds__(256, 2)
attn16(const __half* __restrict__ qkv, const __half* __restrict__ Bt,
       const float* __restrict__ bias, __half* __restrict__ H, int M) {
    extern __shared__ char smc[];
    const int tid  = threadIdx.x;
    const int lane = tid & 31;
    const int w    = tid >> 5;
    const int bm   = blockIdx.y * 128;

    const uint32_t sA = (uint32_t)__cvta_generic_to_shared(smc);
    const uint32_t sB = sA + 4*CHB;

    // all 4 B chunks up front (one commit)
    #pragma unroll
    for (int kc = 0; kc < 4; kc++) {
        #pragma unroll
        for (int l = 0; l < 2; l++) {
            int idx = tid + l * 256;
            int row = idx >> 2;
            int g   = idx & 3;
            cpasync16(sB + (uint32_t)(kc*CHB + row*SMSB + g*16),
                      Bt + (size_t)row * 128 + kc * 32 + g * 8, true);
        }
    }
    cp_commit();

    // attention
    {
        int p_local = tid >> 3;
        int hh = tid & 7;
        int p = (bm >> 2) + p_local;
        if (p < NP) {
            const __half* base = qkv + (size_t)p * 1536 + hh * 16;
            uint4 K0[4], K1[4], V0[4], V1[4];
            #pragma unroll
            for (int ki = 0; ki < 4; ki++) {
                K0[ki] = *(const uint4*)(base + 128 + ki * 384);
                K1[ki] = *(const uint4*)(base + 128 + ki * 384 + 8);
                V0[ki] = *(const uint4*)(base + 256 + ki * 384);
                V1[ki] = *(const uint4*)(base + 256 + ki * 384 + 8);
            }
            #pragma unroll
            for (int qi = 0; qi < 4; qi++) {
                float q[16];
                ld16h(base + qi * 384, q);
                float sc[4];
                float mx = -1e30f;
                #pragma unroll
                for (int ki = 0; ki < 4; ki++) {
                    float s = dotp(q, K0[ki], K1[ki]) * 0.25f;
                    sc[ki] = s;
                    mx = fmaxf(mx, s);
                }
                float sum = 0.0f;
                #pragma unroll
                for (int ki = 0; ki < 4; ki++) { sc[ki] = expf(sc[ki] - mx); sum += sc[ki]; }
                float inv = 1.0f / sum;
                float acco[16];
                #pragma unroll
                for (int d = 0; d < 16; d++) acco[d] = 0.0f;
                #pragma unroll
                for (int ki = 0; ki < 4; ki++)
                    accp(acco, V0[ki], V1[ki], sc[ki] * inv);
                int row = p_local * 4 + qi;
                __half2* d = (__half2*)(smc + (hh >> 1) * CHB + row * SMSB + (hh & 1) * 32);
                #pragma unroll
                for (int c = 0; c < 8; c++)
                    d[c] = __floats2half2_rn(acco[2*c], acco[2*c+1]);
            }
        } else {
            int p_l = tid >> 3, hh2 = tid & 7;
            #pragma unroll
            for (int qi = 0; qi < 4; qi++) {
                int row = p_l * 4 + qi;
                __half2* d = (__half2*)(smc + (hh2 >> 1) * CHB + row * SMSB + (hh2 & 1) * 32);
                #pragma unroll
                for (int c = 0; c < 8; c++) d[c] = __floats2half2_rn(0.0f, 0.0f);
            }
        }
    }

    asm volatile("cp.async.wait_group 0;\n" ::);
    __syncthreads();

    float acc[2][8][4];
    #pragma unroll
    for (int mi = 0; mi < 2; mi++)
        #pragma unroll
        for (int ni = 0; ni < 8; ni++)
            #pragma unroll
            for (int r = 0; r < 4; r++) acc[mi][ni][r] = 0.0f;

    const int lrow = (lane & 7) + ((lane >> 3) & 1) * 8;
    const int lk2  = ((lane >> 4) & 1) * 8;
    const int ra0  = (w & 3) * 32 + lrow;
    const int rb0  = (w >> 2) * 64 + lrow;

    #pragma unroll
    for (int kc = 0; kc < 4; kc++)
        mma_tile16(sA + (uint32_t)(kc*CHB), sB + (uint32_t)(kc*CHB),
                   ra0, rb0, lk2, acc);
    epi12816<1, true>(acc, bias, H, H, M, 128, bm, 0, w & 3, w >> 2, lane);
}

// ---------------- output init + final divide (vectorized) ----------------
__global__ void zero_kernel(float4* __restrict__ out) {
    int i = blockIdx.x * blockDim.x + threadIdx.x;
    int n4 = NCELL * CLN / 4;
    if (i < n4) out[i] = make_float4(0.f, 0.f, 0.f, 0.f);
    else if (i < n4 + NCELL) g_cnt[i - n4] = 0.0f;
}

__global__ void div_kernel(float4* __restrict__ out) {
    int i = blockIdx.x * blockDim.x + threadIdx.x;
    if (i >= NCELL * CLN / 4) return;
    float inv = 1.0f / fmaxf(g_cnt[i >> 7], 1.0f);
    float4 v = out[i];
    v.x *= inv; v.y *= inv; v.z *= inv; v.w *= inv;
    out[i] = v;
}

// ---------------- driver ----------------
extern "C" void kernel_launch(void* const* d_in, const int* in_sizes, int n_in,
                              void* d_out, int out_size) {
    const float* x      = (const float*)d_in[0];
    const float* W_emb  = (const float*)d_in[1];
    const float* b_emb  = (const float*)d_in[2];
    const float* ln1_s  = (const float*)d_in[3];
    const float* ln1_b  = (const float*)d_in[4];
    const float* Wqkv   = (const float*)d_in[5];
    const float* bqkv   = (const float*)d_in[6];
    const float* Wo     = (const float*)d_in[7];
    const float* bo     = (const float*)d_in[8];
    const float* ln2_s  = (const float*)d_in[9];
    const float* ln2_b  = (const float*)d_in[10];
    const float* Wf1    = (const float*)d_in[11];
    const float* bf1    = (const float*)d_in[12];
    const float* Wf2    = (const float*)d_in[13];
    const float* bf2    = (const float*)d_in[14];
    const float* W_comb = (const float*)d_in[15];
    const float* b_comb = (const float*)d_in[16];
    float* out = (float*)d_out;

    __half *p_feat, *p_h, *p_qkv, *p_wt;
    cudaGetSymbolAddress((void**)&p_feat, g_feat);
    cudaGetSymbolAddress((void**)&p_h,    g_h);
    cudaGetSymbolAddress((void**)&p_qkv,  g_qkv);
    cudaGetSymbolAddress((void**)&p_wt,   g_wt);

    const int SMEM   = 8 * CHB;    // 81920
    const int SMEM_F = 20 * CHB;   // 204800
    static bool attr_done = false;
    if (!attr_done) {
        cudaFuncSetAttribute((const void*)gemm_tc16<0,true>,  cudaFuncAttributeMaxDynamicSharedMemorySize, SMEM);
        cudaFuncSetAttribute((const void*)gemm_tc16<3,false>, cudaFuncAttributeMaxDynamicSharedMemorySize, SMEM);
        cudaFuncSetAttribute((const void*)lnA16,  cudaFuncAttributeMaxDynamicSharedMemorySize, SMEM);
        cudaFuncSetAttribute((const void*)attn16, cudaFuncAttributeMaxDynamicSharedMemorySize, SMEM);
        cudaFuncSetAttribute((const void*)ffn16,  cudaFuncAttributeMaxDynamicSharedMemorySize, SMEM_F);
        attr_done = true;
    }

    const int TB = 256;

    // fp16 weight offsets in g_wt
    __half* wembT  = p_wt + 0;        // [512][96]
    __half* wqkvT0 = p_wt + 49152;    // [384][128]
    __half* wqkvT1 = p_wt + 98304;
    __half* woT0   = p_wt + 147456;   // [128][128]
    __half* woT1   = p_wt + 163840;
    __half* wf1T0  = p_wt + 180224;   // [512][128]
    __half* wf1T1  = p_wt + 245760;
    __half* wf2T0  = p_wt + 311296;   // [128][512]
    __half* wf2T1  = p_wt + 376832;
    __half* wcombT = p_wt + 442368;   // [512][512]

    wconv<<<(704512 + TB - 1) / TB, TB>>>(W_emb, Wqkv, Wo, Wf1, Wf2, W_comb);
    // zero out + counts BEFORE feat (feat accumulates counts)
    zero_kernel<<<(NCELL * CLN / 4 + NCELL + TB - 1) / TB, TB>>>((float4*)out);
    feat_kernel<<<(NP + TB - 1) / TB, TB>>>(x);

    // embedding: feat(NP x 96 fp16) @ W_emb -> h (fp16)
    gemm_tc16<0,true><<<dim3(4, (NP + 127) / 128), TB, SMEM>>>(
        p_feat, wembT, b_emb, nullptr, p_h, NP, 512, 96, 96, 96);

    const __half* wqkvT[2] = {wqkvT0, wqkvT1};
    const __half* woT[2]   = {woT0, woT1};
    const __half* wf1T[2]  = {wf1T0, wf1T1};
    const __half* wf2T[2]  = {wf2T0, wf2T1};
    const int MB = (NTOK + 127) / 128;   // 2048

    for (int i = 0; i < 2; i++) {
        lnA16<<<dim3(1, MB), TB, SMEM>>>(p_h, wqkvT[i], bqkv + i * 384,
                                         ln1_s + i * 128, ln1_b + i * 128,
                                         p_qkv, NTOK, 384);
        attn16<<<dim3(1, MB), TB, SMEM>>>(p_qkv, woT[i], bo + i * 128, p_h, NTOK);
        ffn16<<<dim3(1, MB), TB, SMEM_F>>>(p_h, wf1T[i], wf2T[i],
                                           bf1 + i * 512, bf2 + i * 128,
                                           ln2_s + i * 128, ln2_b + i * 128, NTOK);
    }

    // head: h(NP x 512 fp16) @ W_comb -> scattered directly into out (atomicAdd)
    gemm_tc16<3,false><<<dim3(4, (NP + 127) / 128), TB, SMEM>>>(
        p_h, wcombT, b_comb, nullptr, out, NP, 512, 512, 512, 512);

    // final divide by counts
    div_kernel<<<(NCELL * CLN / 4 + TB - 1) / TB, TB>>>((float4*)out);
}

// round 16
// speedup vs baseline: 1.6103x; 1.0696x over previous
#include <cuda_runtime.h>
#include <cuda_fp16.h>
#include <math.h>
#include <stdint.h>

#define NP    65534
#define NTOK  (NP*4)          // 262136 tokens
#define GH    180
#define GW    360
#define NCELL (GH*GW)         // 64800
#define CLN   512

#define SMSB 80               // bytes per smem row (32 fp16 = 64B + 16B pad)
#define CHB  (128*SMSB)       // 10240 bytes per 128x32 fp16 chunk

// ---------------- scratch (device globals: no allocation allowed) ----------------
__device__ __half g_feat[(size_t)NP*96];     // 75 used + zero pad to 96 (fp16)
__device__ int    g_flat[NP];
__device__ __half g_h   [(size_t)NTOK*128];  // transformer state (fp16)
__device__ float  g_cnt [NCELL];
__device__ __half g_wt  [704512];            // transposed fp16 weights

// ---------------- small PTX helpers ----------------
__device__ __forceinline__ void cpasync16(uint32_t dst, const void* src, bool pred) {
    int sz = pred ? 16 : 0;      // sz=0 => zero-fill 16 bytes
    asm volatile("cp.async.cg.shared.global [%0], [%1], 16, %2;\n"
                 :: "r"(dst), "l"(src), "r"(sz));
}
__device__ __forceinline__ void cp_commit() {
    asm volatile("cp.async.commit_group;\n" ::);
}
__device__ __forceinline__ void ldm4(uint32_t& r0, uint32_t& r1, uint32_t& r2, uint32_t& r3, uint32_t addr) {
    asm volatile("ldmatrix.sync.aligned.m8n8.x4.shared.b16 {%0,%1,%2,%3}, [%4];\n"
                 : "=r"(r0), "=r"(r1), "=r"(r2), "=r"(r3) : "r"(addr));
}
__device__ __forceinline__ void mma_f16(float* c, const uint32_t* a, uint32_t b0, uint32_t b1) {
    asm volatile("mma.sync.aligned.m16n8k16.row.col.f32.f16.f16.f32 "
                 "{%0,%1,%2,%3}, {%4,%5,%6,%7}, {%8,%9}, {%0,%1,%2,%3};\n"
                 : "+f"(c[0]), "+f"(c[1]), "+f"(c[2]), "+f"(c[3])
                 : "r"(a[0]), "r"(a[1]), "r"(a[2]), "r"(a[3]), "r"(b0), "r"(b1));
}
__device__ __forceinline__ float gelu_t(float u) {
    return 0.5f * u * (1.0f + tanhf(0.7978845608028654f * (u + 0.044715f * u * u * u)));
}
// unpack 2x uint4 (16 fp16) -> float[16]
__device__ __forceinline__ void unp16(const uint4& a, const uint4& b, float* o) {
    const uint32_t* wa = (const uint32_t*)&a;
    const uint32_t* wb = (const uint32_t*)&b;
    #pragma unroll
    for (int i = 0; i < 4; i++) {
        float2 f = __half22float2(*(const __half2*)&wa[i]);
        o[2*i+0] = f.x; o[2*i+1] = f.y;
    }
    #pragma unroll
    for (int i = 0; i < 4; i++) {
        float2 f = __half22float2(*(const __half2*)&wb[i]);
        o[8+2*i+0] = f.x; o[8+2*i+1] = f.y;
    }
}
// dot(q[16], packed 16-fp16 row)
__device__ __forceinline__ float dotp(const float* q, const uint4& a, const uint4& b) {
    const uint32_t* wa = (const uint32_t*)&a;
    const uint32_t* wb = (const uint32_t*)&b;
    float s = 0.0f;
    #pragma unroll
    for (int i = 0; i < 4; i++) {
        float2 f = __half22float2(*(const __half2*)&wa[i]);
        s += q[2*i] * f.x + q[2*i+1] * f.y;
    }
    #pragma unroll
    for (int i = 0; i < 4; i++) {
        float2 f = __half22float2(*(const __half2*)&wb[i]);
        s += q[8+2*i] * f.x + q[9+2*i] * f.y;
    }
    return s;
}
// o[16] += wv * packed 16-fp16 row
__device__ __forceinline__ void accp(float* o, const uint4& a, const uint4& b, float wv) {
    const uint32_t* wa = (const uint32_t*)&a;
    const uint32_t* wb = (const uint32_t*)&b;
    #pragma unroll
    for (int i = 0; i < 4; i++) {
        float2 f = __half22float2(*(const __half2*)&wa[i]);
        o[2*i]   += wv * f.x;
        o[2*i+1] += wv * f.y;
    }
    #pragma unroll
    for (int i = 0; i < 4; i++) {
        float2 f = __half22float2(*(const __half2*)&wb[i]);
        o[8+2*i] += wv * f.x;
        o[9+2*i] += wv * f.y;
    }
}

// 128x128x32 fp16 mma on one k-chunk. aBase/bBase: smem byte addr of 128x32 chunk.
__device__ __forceinline__ void mma_tile16(uint32_t aBase, uint32_t bBase,
                                           int ra0, int rb0, int lk2,
                                           float acc[2][8][4]) {
    #pragma unroll
    for (int kk = 0; kk < 32; kk += 16) {
        uint32_t a[2][4];
        #pragma unroll
        for (int mi = 0; mi < 2; mi++)
            ldm4(a[mi][0], a[mi][1], a[mi][2], a[mi][3],
                 aBase + (uint32_t)((ra0 + mi * 16) * SMSB + (kk + lk2) * 2));
        uint32_t b0[8], b1[8];
        #pragma unroll
        for (int np = 0; np < 4; np++) {
            uint32_t r0, r1, r2, r3;
            ldm4(r0, r1, r2, r3,
                 bBase + (uint32_t)((rb0 + np * 16) * SMSB + (kk + lk2) * 2));
            b0[2*np] = r0; b0[2*np+1] = r1;
            b1[2*np] = r2; b1[2*np+1] = r3;
        }
        #pragma unroll
        for (int mi = 0; mi < 2; mi++)
            #pragma unroll
            for (int ni = 0; ni < 8; ni++)
                mma_f16(acc[mi][ni], a[mi], b0[ni], b1[ni]);
    }
}

// epilogue for 128-row tiles, warp layout 4x2 (warp tile 32x64)
// EPI: 0=bias->C, 1=bias+fp16residual->C, 2=bias+gelu->C, 3=bias+grid-scatter(atomicAdd fp32)
template<int EPI, bool OUT16>
__device__ __forceinline__ void epi12816(float acc[2][8][4], const float* __restrict__ bias,
                                         const void* __restrict__ R, void* __restrict__ C,
                                         int M, int N, int bm, int bn, int wm, int wn, int lane) {
    const int row0 = bm + wm * 32 + (lane >> 2);
    const int col0 = bn + wn * 64 + (lane & 3) * 2;
    #pragma unroll
    for (int mi = 0; mi < 2; mi++) {
        #pragma unroll
        for (int half = 0; half < 2; half++) {
            int gm = row0 + mi * 16 + half * 8;
            if (gm >= M) continue;
            int cell = (EPI == 3) ? g_flat[gm] : 0;
            #pragma unroll
            for (int ni = 0; ni < 8; ni++) {
                int gn = col0 + ni * 8;
                float v0 = acc[mi][ni][half*2 + 0] + bias[gn];
                float v1 = acc[mi][ni][half*2 + 1] + bias[gn + 1];
                if (EPI == 1) {
                    __half2 rh = *(const __half2*)((const __half*)R + (size_t)gm * N + gn);
                    float2 rf = __half22float2(rh);
                    v0 += rf.x; v1 += rf.y;
                }
                if (EPI == 2) { v0 = gelu_t(v0); v1 = gelu_t(v1); }
                if (EPI == 3) {
                    float* dst = (float*)C + (size_t)cell * CLN + gn;
                    atomicAdd(dst,     v0);
                    atomicAdd(dst + 1, v1);
                } else if (OUT16) {
                    *(__half2*)((__half*)C + (size_t)gm * N + gn) = __floats2half2_rn(v0, v1);
                } else {
                    float2 o; o.x = v0; o.y = v1;
                    *(float2*)((float*)C + (size_t)gm * N + gn) = o;
                }
            }
        }
    }
}

// LayerNorm a 128x128 h tile into smem A chunks (fp16), warp w does rows w*16..+15
__device__ __forceinline__ void ln_to_smem(const __half* __restrict__ H, char* smc,
                                           const float* __restrict__ lns,
                                           const float* __restrict__ lnb,
                                           int bm, int M, int w, int lane) {
    const float4 sc4 = ((const float4*)lns)[lane];
    const float4 bc4 = ((const float4*)lnb)[lane];
    #pragma unroll
    for (int rr = 0; rr < 16; rr++) {
        int row = w * 16 + rr;
        int gm  = bm + row;
        float v0 = 0.0f, v1 = 0.0f, v2 = 0.0f, v3 = 0.0f;
        if (gm < M) {
            uint2 u = *(const uint2*)(H + (size_t)gm * 128 + lane * 4);
            float2 fa = __half22float2(*(const __half2*)&u.x);
            float2 fb = __half22float2(*(const __half2*)&u.y);
            v0 = fa.x; v1 = fa.y; v2 = fb.x; v3 = fb.y;
        }
        float sum = v0 + v1 + v2 + v3;
        float sq  = v0*v0 + v1*v1 + v2*v2 + v3*v3;
        #pragma unroll
        for (int o = 16; o > 0; o >>= 1) {
            sum += __shfl_xor_sync(0xffffffffu, sum, o);
            sq  += __shfl_xor_sync(0xffffffffu, sq,  o);
        }
        float mean = sum * (1.0f/128.0f);
        float var  = sq  * (1.0f/128.0f) - mean * mean;
        float r = rsqrtf(var + 1e-5f);
        float o0 = (v0 - mean) * r * sc4.x + bc4.x;
        float o1 = (v1 - mean) * r * sc4.y + bc4.y;
        float o2 = (v2 - mean) * r * sc4.z + bc4.z;
        float o3 = (v3 - mean) * r * sc4.w + bc4.w;
        __half2* d = (__half2*)(smc + (lane >> 3) * CHB + row * SMSB + (lane & 7) * 8);
        d[0] = __floats2half2_rn(o0, o1);
        d[1] = __floats2half2_rn(o2, o3);
    }
}

// ---------------- feature build + grid index + counts (fp16 output) ----------------
__global__ void feat_kernel(const float* __restrict__ x) {
    int i = blockIdx.x * blockDim.x + threadIdx.x;
    if (i >= NP) return;
    const float* xr = x + (size_t)i * 24;
    float lat = xr[0];
    if (lat == -90.0f) lat += 0.0001f;
    float lon = xr[1];
    float t   = xr[2];

    int lati = (int)floorf(90.0f - lat);
    int loni = (int)fmodf(180.0f + floorf(lon + 180.0f), 360.0f);
    int cell = lati * GW + loni;
    g_flat[i] = cell;
    atomicAdd(&g_cnt[cell], 1.0f);

    __half* f = g_feat + (size_t)i * 96;
    f[0] = __float2half_rn(lat * (1.0f/90.0f));
    f[1] = __float2half_rn(lon * (1.0f/180.0f));
    f[2] = __float2half_rn(t   * (1.0f/12.0f));
    #pragma unroll
    for (int j = 3; j < 24; j++) f[j] = __float2half_rn(xr[j]);

    float p0 = -lat - floorf(-lat);
    float p1 =  lon - floorf(lon);
    float p2 =  t + 1.0f;
    f[24] = __float2half_rn(p0); f[25] = __float2half_rn(p1); f[26] = __float2half_rn(p2);
    float p[3] = {p0, p1, p2};
    #pragma unroll
    for (int c = 0; c < 3; c++) {
        float fr = 3.14159274101257324f;
        #pragma unroll
        for (int k = 0; k < 8; k++) {
            float ang = p[c] * fr;
            f[27 + c*8 + k] = __float2half_rn(sinf(ang));
            f[51 + c*8 + k] = __float2half_rn(cosf(ang));
            fr *= 2.0f;
        }
    }
    #pragma unroll
    for (int j = 75; j < 96; j++) f[j] = __float2half_rn(0.0f);
}

// ---------------- all-in-one weight transpose + fp16 round ----------------
__global__ void wconv(const float* __restrict__ W_emb, const float* __restrict__ Wqkv,
                      const float* __restrict__ Wo, const float* __restrict__ Wf1,
                      const float* __restrict__ Wf2, const float* __restrict__ W_comb) {
    int idx = blockIdx.x * blockDim.x + threadIdx.x;
    if (idx >= 704512) return;
    const float* srcs[6] = {W_emb, Wqkv, Wo, Wf1, Wf2, W_comb};
    const int sel [10] = {0,1,1,2,2,3,3,4,4,5};
    const int soff[10] = {0,0,49152,0,16384,0,65536,0,65536,0};
    const int Kt  [10] = {75,128,128,128,128,128,128,512,512,512};
    const int Nt  [10] = {512,384,384,128,128,512,512,128,128,512};
    const int Kp  [10] = {96,128,128,128,128,128,128,512,512,512};
    const int dst [10] = {0,49152,98304,147456,163840,180224,245760,311296,376832,442368};
    int m = 0;
    #pragma unroll
    for (int i = 1; i < 10; i++) if (idx >= dst[i]) m = i;
    int local = idx - dst[m];
    int n = local / Kp[m];
    int k = local - n * Kp[m];
    float v = (k < Kt[m]) ? srcs[sel[m]][soff[m] + (size_t)k * Nt[m] + n] : 0.0f;
    g_wt[idx] = __float2half_rn(v);
}

// ---------------- generic fp16 GEMM, R12 scheme: ring-4, depth-2, 1 sync/chunk ----------------
template<int EPI, bool OUT16>
__global__ void __launch_bounds__(256, 2)
gemm_tc16(const __half* __restrict__ A, const __half* __restrict__ Bt,
          const float* __restrict__ bias, const void* __restrict__ R,
          void* __restrict__ C, int M, int N, int K, int lda, int ldb) {
    extern __shared__ char smc[];
    const int tid  = threadIdx.x;
    const int lane = tid & 31;
    const int w    = tid >> 5;
    const int wm   = w & 3;
    const int wn   = w >> 2;
    const int bm   = blockIdx.y * 128;
    const int bn   = blockIdx.x * 128;

    const uint32_t sA = (uint32_t)__cvta_generic_to_shared(smc);
    const uint32_t sB = sA + 4*CHB;

    float acc[2][8][4];
    #pragma unroll
    for (int mi = 0; mi < 2; mi++)
        #pragma unroll
        for (int ni = 0; ni < 8; ni++)
            #pragma unroll
            for (int r = 0; r < 4; r++) acc[mi][ni][r] = 0.0f;

    const int lrow = (lane & 7) + ((lane >> 3) & 1) * 8;
    const int lk2  = ((lane >> 4) & 1) * 8;
    const int ra0  = wm * 32 + lrow;
    const int rb0  = wn * 64 + lrow;
    const int nc   = K >> 5;

    auto load_chunk = [&](int c) {
        int buf = c & 3;
        int k0  = c * 32;
        #pragma unroll
        for (int l = 0; l < 2; l++) {
            int idx = tid + l * 256;      // 0..511
            int row = idx >> 2;
            int g   = idx & 3;
            bool pa = (bm + row) < M;
            const void* src = pa ? (const void*)(A + (size_t)(bm + row) * lda + k0 + g * 8)
                                 : (const void*)A;
            cpasync16(sA + (uint32_t)(buf*CHB + row*SMSB + g*16), src, pa);
        }
        #pragma unroll
        for (int l = 0; l < 2; l++) {
            int idx = tid + l * 256;
            int row = idx >> 2;
            int g   = idx & 3;
            cpasync16(sB + (uint32_t)(buf*CHB + row*SMSB + g*16),
                      Bt + (size_t)(bn + row) * ldb + k0 + g * 8, true);
        }
        cp_commit();
    };

    load_chunk(0);
    if (nc > 1) load_chunk(1);
    for (int c = 0; c < nc; c++) {
        if (c + 2 < nc) {
            load_chunk(c + 2);
            asm volatile("cp.async.wait_group 2;\n" ::);
        } else if (c + 1 < nc) {
            asm volatile("cp.async.wait_group 1;\n" ::);
        } else {
            asm volatile("cp.async.wait_group 0;\n" ::);
        }
        __syncthreads();                          // publish chunk c + fence ring reuse
        int buf = c & 3;
        mma_tile16(sA + (uint32_t)(buf*CHB), sB + (uint32_t)(buf*CHB), ra0, rb0, lk2, acc);
    }
    epi12816<EPI, OUT16>(acc, bias, R, C, M, N, bm, bn, wm, wn, lane);
}

// ---------------- fused LN1 + QKV + attention + o-proj + residual ----------------
// smem: A[4ch]=40K (LN'd h, later attn-out) | Q[12ch]=120K (qkv) | W[4ch]=40K (B ring / Wo)
// grid (1, M/128), 256 threads, occ 1.
__global__ void __launch_bounds__(256, 1)
lqa16(__half* __restrict__ H, const __half* __restrict__ Bq,
      const __half* __restrict__ Bo, const float* __restrict__ bqkv,
      const float* __restrict__ bo, const float* __restrict__ lns,
      const float* __restrict__ lnb, int M) {
    extern __shared__ char smc[];
    const int tid  = threadIdx.x;
    const int lane = tid & 31;
    const int w    = tid >> 5;
    const int wm   = w & 3;
    const int wn   = w >> 2;
    const int bm   = blockIdx.y * 128;

    const uint32_t sA = (uint32_t)__cvta_generic_to_shared(smc);
    const uint32_t sW = sA + 16*CHB;
    char* smq = smc + 4*CHB;

    // qkv weight chunk s (s = nb*4 + kc) into ring buf s&3
    auto loadBq = [&](int s) {
        int nb = s >> 2, kc = s & 3, buf = s & 3;
        #pragma unroll
        for (int l = 0; l < 2; l++) {
            int idx = tid + l * 256;
            int row = idx >> 2;
            int g   = idx & 3;
            cpasync16(sW + (uint32_t)(buf*CHB + row*SMSB + g*16),
                      Bq + (size_t)(nb * 128 + row) * 128 + kc * 32 + g * 8, true);
        }
        cp_commit();
    };

    loadBq(0);
    loadBq(1);

    ln_to_smem(H, smc, lns, lnb, bm, M, w, lane);

    const int lrow = (lane & 7) + ((lane >> 3) & 1) * 8;
    const int lk2  = ((lane >> 4) & 1) * 8;
    const int ra0  = wm * 32 + lrow;
    const int rb0  = wn * 64 + lrow;

    // QKV GEMM (N=384): 12 B chunks, R12 ring-4/depth-2; epilogue -> sQ smem chunks
    {
        float acc[2][8][4];
        for (int s = 0; s < 12; s++) {
            if (s + 2 < 12) {
                loadBq(s + 2);
                asm volatile("cp.async.wait_group 2;\n" ::);
            } else if (s + 1 < 12) {
                asm volatile("cp.async.wait_group 1;\n" ::);
            } else {
                asm volatile("cp.async.wait_group 0;\n" ::);
            }
            __syncthreads();              // publish B chunk s (and LN tile at s=0)
            if ((s & 3) == 0) {
                #pragma unroll
                for (int mi = 0; mi < 2; mi++)
                    #pragma unroll
                    for (int ni = 0; ni < 8; ni++)
                        #pragma unroll
                        for (int r = 0; r < 4; r++) acc[mi][ni][r] = 0.0f;
            }
            mma_tile16(sA + (uint32_t)((s & 3)*CHB), sW + (uint32_t)((s & 3)*CHB),
                       ra0, rb0, lk2, acc);
            if ((s & 3) == 3) {
                // bias + fp16 round -> sQ chunk layout (same rounding as old gmem path)
                int nb = s >> 2;
                const int r0 = wm * 32 + (lane >> 2);
                const int c0 = wn * 64 + (lane & 3) * 2;
                #pragma unroll
                for (int mi = 0; mi < 2; mi++) {
                    #pragma unroll
                    for (int half = 0; half < 2; half++) {
                        int row = r0 + mi * 16 + half * 8;
                        #pragma unroll
                        for (int ni = 0; ni < 8; ni++) {
                            int col = c0 + ni * 8;
                            int gcol = nb * 128 + col;
                            float v0 = acc[mi][ni][half*2 + 0] + bqkv[gcol];
                            float v1 = acc[mi][ni][half*2 + 1] + bqkv[gcol + 1];
                            *(__half2*)(smq + (gcol >> 5) * CHB + row * SMSB + (gcol & 31) * 2)
                                = __floats2half2_rn(v0, v1);
                        }
                    }
                }
            }
        }
    }

    __syncthreads();   // all mma reads of sA/sW done; sQ epi writes published

    // prefetch Wo (4 chunks into sW ring, one group) — lands during attention
    #pragma unroll
    for (int kc = 0; kc < 4; kc++) {
        #pragma unroll
        for (int l = 0; l < 2; l++) {
            int idx = tid + l * 256;
            int row = idx >> 2;
            int g   = idx & 3;
            cpasync16(sW + (uint32_t)(kc*CHB + row*SMSB + g*16),
                      Bo + (size_t)row * 128 + kc * 32 + g * 8, true);
        }
    }
    cp_commit();

    // attention from sQ; output overwrites sA chunks
    {
        int p_local = tid >> 3;
        int hh = tid & 7;
        int p = (bm >> 2) + p_local;
        int hc   = hh >> 1;              // chunk within a 128-col group
        int hoff = (hh & 1) * 32;        // byte offset within chunk row
        if (p < NP) {
            uint4 K0[4], K1[4], V0[4], V1[4];
            #pragma unroll
            for (int ki = 0; ki < 4; ki++) {
                const char* rk = smq + (4 + hc) * CHB + (p_local * 4 + ki) * SMSB + hoff;
                const char* rv = smq + (8 + hc) * CHB + (p_local * 4 + ki) * SMSB + hoff;
                K0[ki] = *(const uint4*)rk;
                K1[ki] = *(const uint4*)(rk + 16);
                V0[ki] = *(const uint4*)rv;
                V1[ki] = *(const uint4*)(rv + 16);
            }
            #pragma unroll
            for (int qi = 0; qi < 4; qi++) {
                int row = p_local * 4 + qi;
                const char* rq = smq + hc * CHB + row * SMSB + hoff;
                uint4 Q0 = *(const uint4*)rq;
                uint4 Q1 = *(const uint4*)(rq + 16);
                float q[16];
                unp16(Q0, Q1, q);
                float sc[4];
                float mx = -1e30f;
                #pragma unroll
                for (int ki = 0; ki < 4; ki++) {
                    float s = dotp(q, K0[ki], K1[ki]) * 0.25f;
                    sc[ki] = s;
                    mx = fmaxf(mx, s);
                }
                float sum = 0.0f;
                #pragma unroll
                for (int ki = 0; ki < 4; ki++) { sc[ki] = expf(sc[ki] - mx); sum += sc[ki]; }
                float inv = 1.0f / sum;
                float acco[16];
                #pragma unroll
                for (int d = 0; d < 16; d++) acco[d] = 0.0f;
                #pragma unroll
                for (int ki = 0; ki < 4; ki++)
                    accp(acco, V0[ki], V1[ki], sc[ki] * inv);
                __half2* d = (__half2*)(smc + hc * CHB + row * SMSB + hoff);
                #pragma unroll
                for (int c = 0; c < 8; c++)
                    d[c] = __floats2half2_rn(acco[2*c], acco[2*c+1]);
            }
        } else {
            #pragma unroll
            for (int qi = 0; qi < 4; qi++) {
                int row = p_local * 4 + qi;
                __half2* d = (__half2*)(smc + hc * CHB + row * SMSB + hoff);
                #pragma unroll
                for (int c = 0; c < 8; c++) d[c] = __floats2half2_rn(0.0f, 0.0f);
            }
        }
    }

    asm volatile("cp.async.wait_group 0;\n" ::);   // Wo resident
    __syncthreads();                               // publish attn-out + Wo

    // o-proj: attn_out(sA) x Wo(sW) + bo + residual h -> H
    {
        float acc[2][8][4];
        #pragma unroll
        for (int mi = 0; mi < 2; mi++)
            #pragma unroll
            for (int ni = 0; ni < 8; ni++)
                #pragma unroll
                for (int r = 0; r < 4; r++) acc[mi][ni][r] = 0.0f;
        #pragma unroll
        for (int kc = 0; kc < 4; kc++)
            mma_tile16(sA + (uint32_t)(kc*CHB), sW + (uint32_t)(kc*CHB),
                       ra0, rb0, lk2, acc);
        epi12816<1, true>(acc, bo, H, H, M, 128, bm, 0, wm, wn, lane);
    }
}

// ---------------- fused LN2 + FF1 + GELU + FF2 + residual: all in one CTA ----------------
// smem: A[4ch]=40K | G[4ch]=40K | B1[4ch]=40K | B2[2][4ch]=80K  = 200KB -> occ 1
__global__ void __launch_bounds__(256, 1)
ffn16(__half* __restrict__ H, const __half* __restrict__ B1t,
      const __half* __restrict__ B2t, const float* __restrict__ bf1,
      const float* __restrict__ bf2, const float* __restrict__ lns,
      const float* __restrict__ lnb, int M) {
    extern __shared__ char smc[];
    const int tid  = threadIdx.x;
    const int lane = tid & 31;
    const int w    = tid >> 5;
    const int wm   = w & 3;
    const int wn   = w >> 2;
    const int bm   = blockIdx.y * 128;

    const uint32_t sA  = (uint32_t)__cvta_generic_to_shared(smc);
    const uint32_t sG  = sA + 4*CHB;
    const uint32_t sB1 = sA + 8*CHB;
    const uint32_t sB2 = sA + 12*CHB;
    char* smG = smc + 4*CHB;

    auto loadB1 = [&](int nb) {
        #pragma unroll
        for (int kc = 0; kc < 4; kc++) {
            #pragma unroll
            for (int l = 0; l < 2; l++) {
                int idx = tid + l * 256;
                int row = idx >> 2;
                int g   = idx & 3;
                cpasync16(sB1 + (uint32_t)(kc*CHB + row*SMSB + g*16),
                          B1t + (size_t)(nb * 128 + row) * 128 + kc * 32 + g * 8, true);
            }
        }
        cp_commit();
    };
    auto loadB2 = [&](int nb, int buf) {
        #pragma unroll
        for (int kc = 0; kc < 4; kc++) {
            #pragma unroll
            for (int l = 0; l < 2; l++) {
                int idx = tid + l * 256;
                int row = idx >> 2;
                int g   = idx & 3;
                cpasync16(sB2 + (uint32_t)(buf*4*CHB + kc*CHB + row*SMSB + g*16),
                          B2t + (size_t)row * 512 + nb * 128 + kc * 32 + g * 8, true);
            }
        }
        cp_commit();
    };

    loadB1(0);
    loadB2(0, 0);

    ln_to_smem(H, smc, lns, lnb, bm, M, w, lane);

    asm volatile("cp.async.wait_group 0;\n" ::);
    __syncthreads();    // B1[0], B2[0], LN tile all published

    const int lrow = (lane & 7) + ((lane >> 3) & 1) * 8;
    const int lk2  = ((lane >> 4) & 1) * 8;
    const int ra0  = wm * 32 + lrow;
    const int rb0  = wn * 64 + lrow;

    float acc2[2][8][4];
    #pragma unroll
    for (int mi = 0; mi < 2; mi++)
        #pragma unroll
        for (int ni = 0; ni < 8; ni++)
            #pragma unroll
            for (int r = 0; r < 4; r++) acc2[mi][ni][r] = 0.0f;

    for (int nb = 0; nb < 4; nb++) {
        if (nb > 0) {
            asm volatile("cp.async.wait_group 0;\n" ::);
            __syncthreads();   // publish B1[nb], B2[nb&1]; FF2[nb-1] done -> G writable
        }
        // FF1: A x B1[nb] -> acc1 (full 128x128 tile, 4 k-chunks)
        float acc1[2][8][4];
        #pragma unroll
        for (int mi = 0; mi < 2; mi++)
            #pragma unroll
            for (int ni = 0; ni < 8; ni++)
                #pragma unroll
                for (int r = 0; r < 4; r++) acc1[mi][ni][r] = 0.0f;
        #pragma unroll
        for (int kc = 0; kc < 4; kc++)
            mma_tile16(sA + (uint32_t)(kc*CHB), sB1 + (uint32_t)(kc*CHB),
                       ra0, rb0, lk2, acc1);

        // gelu + bias -> G smem
        {
            const int r0 = wm * 32 + (lane >> 2);
            const int c0 = wn * 64 + (lane & 3) * 2;
            #pragma unroll
            for (int mi = 0; mi < 2; mi++) {
                #pragma unroll
                for (int half = 0; half < 2; half++) {
                    int row = r0 + mi * 16 + half * 8;
                    #pragma unroll
                    for (int ni = 0; ni < 8; ni++) {
                        int col = c0 + ni * 8;
                        float v0 = gelu_t(acc1[mi][ni][half*2 + 0] + bf1[nb * 128 + col]);
                        float v1 = gelu_t(acc1[mi][ni][half*2 + 1] + bf1[nb * 128 + col + 1]);
                        *(__half2*)(smG + ((col >> 5) * CHB) + row * SMSB + (col & 31) * 2)
                            = __floats2half2_rn(v0, v1);
                    }
                }
            }
        }
        __syncthreads();   // publish G; all warps done with B1[nb]

        if (nb < 3) {
            loadB1(nb + 1);
            loadB2(nb + 1, (nb + 1) & 1);
        }

        // FF2: G x B2[nb&1] -> acc2 accumulate
        #pragma unroll
        for (int kc = 0; kc < 4; kc++)
            mma_tile16(sG + (uint32_t)(kc*CHB),
                       sB2 + (uint32_t)((nb & 1)*4*CHB + kc*CHB),
                       ra0, rb0, lk2, acc2);
    }

    epi12816<1, true>(acc2, bf2, H, H, M, 128, bm, 0, wm, wn, lane);
}

// ---------------- output init + final divide (vectorized) ----------------
__global__ void zero_kernel(float4* __restrict__ out) {
    int i = blockIdx.x * blockDim.x + threadIdx.x;
    int n4 = NCELL * CLN / 4;
    if (i < n4) out[i] = make_float4(0.f, 0.f, 0.f, 0.f);
    else if (i < n4 + NCELL) g_cnt[i - n4] = 0.0f;
}

__global__ void div_kernel(float4* __restrict__ out) {
    int i = blockIdx.x * blockDim.x + threadIdx.x;
    if (i >= NCELL * CLN / 4) return;
    float inv = 1.0f / fmaxf(g_cnt[i >> 7], 1.0f);
    float4 v = out[i];
    v.x *= inv; v.y *= inv; v.z *= inv; v.w *= inv;
    out[i] = v;
}

// ---------------- driver ----------------
extern "C" void kernel_launch(void* const* d_in, const int* in_sizes, int n_in,
                              void* d_out, int out_size) {
    const float* x      = (const float*)d_in[0];
    const float* W_emb  = (const float*)d_in[1];
    const float* b_emb  = (const float*)d_in[2];
    const float* ln1_s  = (const float*)d_in[3];
    const float* ln1_b  = (const float*)d_in[4];
    const float* Wqkv   = (const float*)d_in[5];
    const float* bqkv   = (const float*)d_in[6];
    const float* Wo     = (const float*)d_in[7];
    const float* bo     = (const float*)d_in[8];
    const float* ln2_s  = (const float*)d_in[9];
    const float* ln2_b  = (const float*)d_in[10];
    const float* Wf1    = (const float*)d_in[11];
    const float* bf1    = (const float*)d_in[12];
    const float* Wf2    = (const float*)d_in[13];
    const float* bf2    = (const float*)d_in[14];
    const float* W_comb = (const float*)d_in[15];
    const float* b_comb = (const float*)d_in[16];
    float* out = (float*)d_out;

    __half *p_feat, *p_h, *p_wt;
    cudaGetSymbolAddress((void**)&p_feat, g_feat);
    cudaGetSymbolAddress((void**)&p_h,    g_h);
    cudaGetSymbolAddress((void**)&p_wt,   g_wt);

    const int SMEM   = 8 * CHB;    // 81920
    const int SMEM_F = 20 * CHB;   // 204800
    static bool attr_done = false;
    if (!attr_done) {
        cudaFuncSetAttribute((const void*)gemm_tc16<0,true>,  cudaFuncAttributeMaxDynamicSharedMemorySize, SMEM);
        cudaFuncSetAttribute((const void*)gemm_tc16<3,false>, cudaFuncAttributeMaxDynamicSharedMemorySize, SMEM);
        cudaFuncSetAttribute((const void*)lqa16, cudaFuncAttributeMaxDynamicSharedMemorySize, SMEM_F);
        cudaFuncSetAttribute((const void*)ffn16, cudaFuncAttributeMaxDynamicSharedMemorySize, SMEM_F);
        attr_done = true;
    }

    const int TB = 256;

    // fp16 weight offsets in g_wt
    __half* wembT  = p_wt + 0;        // [512][96]
    __half* wqkvT0 = p_wt + 49152;    // [384][128]
    __half* wqkvT1 = p_wt + 98304;
    __half* woT0   = p_wt + 147456;   // [128][128]
    __half* woT1   = p_wt + 163840;
    __half* wf1T0  = p_wt + 180224;   // [512][128]
    __half* wf1T1  = p_wt + 245760;
    __half* wf2T0  = p_wt + 311296;   // [128][512]
    __half* wf2T1  = p_wt + 376832;
    __half* wcombT = p_wt + 442368;   // [512][512]

    wconv<<<(704512 + TB - 1) / TB, TB>>>(W_emb, Wqkv, Wo, Wf1, Wf2, W_comb);
    // zero out + counts BEFORE feat (feat accumulates counts)
    zero_kernel<<<(NCELL * CLN / 4 + NCELL + TB - 1) / TB, TB>>>((float4*)out);
    feat_kernel<<<(NP + TB - 1) / TB, TB>>>(x);

    // embedding: feat(NP x 96 fp16) @ W_emb -> h (fp16)
    gemm_tc16<0,true><<<dim3(4, (NP + 127) / 128), TB, SMEM>>>(
        p_feat, wembT, b_emb, nullptr, p_h, NP, 512, 96, 96, 96);

    const __half* wqkvT[2] = {wqkvT0, wqkvT1};
    const __half* woT[2]   = {woT0, woT1};
    const __half* wf1T[2]  = {wf1T0, wf1T1};
    const __half* wf2T[2]  = {wf2T0, wf2T1};
    const int MB = (NTOK + 127) / 128;   // 2048

    for (int i = 0; i < 2; i++) {
        // LN1 + QKV + attention + o-proj + residual, fully fused
        lqa16<<<dim3(1, MB), TB, SMEM_F>>>(p_h, wqkvT[i], woT[i],
                                           bqkv + i * 384, bo + i * 128,
                                           ln1_s + i * 128, ln1_b + i * 128, NTOK);
        // LN2 + FF1 + GELU + FF2 + residual, fully fused
        ffn16<<<dim3(1, MB), TB, SMEM_F>>>(p_h, wf1T[i], wf2T[i],
                                           bf1 + i * 512, bf2 + i * 128,
                                           ln2_s + i * 128, ln2_b + i * 128, NTOK);
    }

    // head: h(NP x 512 fp16) @ W_comb -> scattered directly into out (atomicAdd)
    gemm_tc16<3,false><<<dim3(4, (NP + 127) / 128), TB, SMEM>>>(
        p_h, wcombT, b_comb, nullptr, out, NP, 512, 512, 512, 512);

    // final divide by counts
    div_kernel<<<(NCELL * CLN / 4 + TB - 1) / TB, TB>>>((float4*)out);
}

// round 17
// speedup vs baseline: 1.6858x; 1.0469x over previous
#include <cuda_runtime.h>
#include <cuda_fp16.h>
#include <math.h>
#include <stdint.h>

#define NP    65534
#define NTOK  (NP*4)          // 262136 tokens
#define GH    180
#define GW    360
#define NCELL (GH*GW)         // 64800
#define CLN   512

#define SMSB 80               // bytes per smem row (32 fp16 = 64B + 16B pad)
#define CHB  (128*SMSB)       // 10240 bytes per 128x32 fp16 chunk

// ---------------- scratch (device globals: no allocation allowed) ----------------
__device__ __half g_feat[(size_t)NP*96];     // 75 used + zero pad to 96 (fp16)
__device__ int    g_flat[NP];
__device__ __half g_h   [(size_t)NTOK*128];  // transformer state (fp16)
__device__ float  g_cnt [NCELL];
__device__ __half g_wt  [704512];            // transposed fp16 weights

// ---------------- small PTX helpers ----------------
__device__ __forceinline__ void cpasync16(uint32_t dst, const void* src, bool pred) {
    int sz = pred ? 16 : 0;      // sz=0 => zero-fill 16 bytes
    asm volatile("cp.async.cg.shared.global [%0], [%1], 16, %2;\n"
                 :: "r"(dst), "l"(src), "r"(sz));
}
__device__ __forceinline__ void cp_commit() {
    asm volatile("cp.async.commit_group;\n" ::);
}
__device__ __forceinline__ void ldm4(uint32_t& r0, uint32_t& r1, uint32_t& r2, uint32_t& r3, uint32_t addr) {
    asm volatile("ldmatrix.sync.aligned.m8n8.x4.shared.b16 {%0,%1,%2,%3}, [%4];\n"
                 : "=r"(r0), "=r"(r1), "=r"(r2), "=r"(r3) : "r"(addr));
}
__device__ __forceinline__ void mma_f16(float* c, const uint32_t* a, uint32_t b0, uint32_t b1) {
    asm volatile("mma.sync.aligned.m16n8k16.row.col.f32.f16.f16.f32 "
                 "{%0,%1,%2,%3}, {%4,%5,%6,%7}, {%8,%9}, {%0,%1,%2,%3};\n"
                 : "+f"(c[0]), "+f"(c[1]), "+f"(c[2]), "+f"(c[3])
                 : "r"(a[0]), "r"(a[1]), "r"(a[2]), "r"(a[3]), "r"(b0), "r"(b1));
}
__device__ __forceinline__ float gelu_t(float u) {
    return 0.5f * u * (1.0f + tanhf(0.7978845608028654f * (u + 0.044715f * u * u * u)));
}
// unpack 2x uint4 (16 fp16) -> float[16]
__device__ __forceinline__ void unp16(const uint4& a, const uint4& b, float* o) {
    const uint32_t* wa = (const uint32_t*)&a;
    const uint32_t* wb = (const uint32_t*)&b;
    #pragma unroll
    for (int i = 0; i < 4; i++) {
        float2 f = __half22float2(*(const __half2*)&wa[i]);
        o[2*i+0] = f.x; o[2*i+1] = f.y;
    }
    #pragma unroll
    for (int i = 0; i < 4; i++) {
        float2 f = __half22float2(*(const __half2*)&wb[i]);
        o[8+2*i+0] = f.x; o[8+2*i+1] = f.y;
    }
}
// dot(q[16], packed 16-fp16 row)
__device__ __forceinline__ float dotp(const float* q, const uint4& a, const uint4& b) {
    const uint32_t* wa = (const uint32_t*)&a;
    const uint32_t* wb = (const uint32_t*)&b;
    float s = 0.0f;
    #pragma unroll
    for (int i = 0; i < 4; i++) {
        float2 f = __half22float2(*(const __half2*)&wa[i]);
        s += q[2*i] * f.x + q[2*i+1] * f.y;
    }
    #pragma unroll
    for (int i = 0; i < 4; i++) {
        float2 f = __half22float2(*(const __half2*)&wb[i]);
        s += q[8+2*i] * f.x + q[9+2*i] * f.y;
    }
    return s;
}
// o[16] += wv * packed 16-fp16 row
__device__ __forceinline__ void accp(float* o, const uint4& a, const uint4& b, float wv) {
    const uint32_t* wa = (const uint32_t*)&a;
    const uint32_t* wb = (const uint32_t*)&b;
    #pragma unroll
    for (int i = 0; i < 4; i++) {
        float2 f = __half22float2(*(const __half2*)&wa[i]);
        o[2*i]   += wv * f.x;
        o[2*i+1] += wv * f.y;
    }
    #pragma unroll
    for (int i = 0; i < 4; i++) {
        float2 f = __half22float2(*(const __half2*)&wb[i]);
        o[8+2*i] += wv * f.x;
        o[9+2*i] += wv * f.y;
    }
}

// 128x128x32 fp16 mma on one k-chunk. aBase/bBase: smem byte addr of 128x32 chunk.
__device__ __forceinline__ void mma_tile16(uint32_t aBase, uint32_t bBase,
                                           int ra0, int rb0, int lk2,
                                           float acc[2][8][4]) {
    #pragma unroll
    for (int kk = 0; kk < 32; kk += 16) {
        uint32_t a[2][4];
        #pragma unroll
        for (int mi = 0; mi < 2; mi++)
            ldm4(a[mi][0], a[mi][1], a[mi][2], a[mi][3],
                 aBase + (uint32_t)((ra0 + mi * 16) * SMSB + (kk + lk2) * 2));
        uint32_t b0[8], b1[8];
        #pragma unroll
        for (int np = 0; np < 4; np++) {
            uint32_t r0, r1, r2, r3;
            ldm4(r0, r1, r2, r3,
                 bBase + (uint32_t)((rb0 + np * 16) * SMSB + (kk + lk2) * 2));
            b0[2*np] = r0; b0[2*np+1] = r1;
            b1[2*np] = r2; b1[2*np+1] = r3;
        }
        #pragma unroll
        for (int mi = 0; mi < 2; mi++)
            #pragma unroll
            for (int ni = 0; ni < 8; ni++)
                mma_f16(acc[mi][ni], a[mi], b0[ni], b1[ni]);
    }
}

// epilogue for 128-row tiles, warp layout 4x2 (warp tile 32x64)
// EPI: 0=bias->C, 1=bias+fp16residual->C, 2=bias+gelu->C, 3=bias+grid-scatter(atomicAdd fp32)
template<int EPI, bool OUT16>
__device__ __forceinline__ void epi12816(float acc[2][8][4], const float* __restrict__ bias,
                                         const void* __restrict__ R, void* __restrict__ C,
                                         int M, int N, int bm, int bn, int wm, int wn, int lane) {
    const int row0 = bm + wm * 32 + (lane >> 2);
    const int col0 = bn + wn * 64 + (lane & 3) * 2;
    #pragma unroll
    for (int mi = 0; mi < 2; mi++) {
        #pragma unroll
        for (int half = 0; half < 2; half++) {
            int gm = row0 + mi * 16 + half * 8;
            if (gm >= M) continue;
            int cell = (EPI == 3) ? g_flat[gm] : 0;
            #pragma unroll
            for (int ni = 0; ni < 8; ni++) {
                int gn = col0 + ni * 8;
                float v0 = acc[mi][ni][half*2 + 0] + bias[gn];
                float v1 = acc[mi][ni][half*2 + 1] + bias[gn + 1];
                if (EPI == 1) {
                    __half2 rh = *(const __half2*)((const __half*)R + (size_t)gm * N + gn);
                    float2 rf = __half22float2(rh);
                    v0 += rf.x; v1 += rf.y;
                }
                if (EPI == 2) { v0 = gelu_t(v0); v1 = gelu_t(v1); }
                if (EPI == 3) {
                    float* dst = (float*)C + (size_t)cell * CLN + gn;
                    atomicAdd(dst,     v0);
                    atomicAdd(dst + 1, v1);
                } else if (OUT16) {
                    *(__half2*)((__half*)C + (size_t)gm * N + gn) = __floats2half2_rn(v0, v1);
                } else {
                    float2 o; o.x = v0; o.y = v1;
                    *(float2*)((float*)C + (size_t)gm * N + gn) = o;
                }
            }
        }
    }
}

// LayerNorm a 128x128 h tile (from gmem) into smem A chunks (fp16)
__device__ __forceinline__ void ln_to_smem(const __half* __restrict__ H, char* smc,
                                           const float* __restrict__ lns,
                                           const float* __restrict__ lnb,
                                           int bm, int M, int w, int lane) {
    const float4 sc4 = ((const float4*)lns)[lane];
    const float4 bc4 = ((const float4*)lnb)[lane];
    #pragma unroll
    for (int rr = 0; rr < 16; rr++) {
        int row = w * 16 + rr;
        int gm  = bm + row;
        float v0 = 0.0f, v1 = 0.0f, v2 = 0.0f, v3 = 0.0f;
        if (gm < M) {
            uint2 u = *(const uint2*)(H + (size_t)gm * 128 + lane * 4);
            float2 fa = __half22float2(*(const __half2*)&u.x);
            float2 fb = __half22float2(*(const __half2*)&u.y);
            v0 = fa.x; v1 = fa.y; v2 = fb.x; v3 = fb.y;
        }
        float sum = v0 + v1 + v2 + v3;
        float sq  = v0*v0 + v1*v1 + v2*v2 + v3*v3;
        #pragma unroll
        for (int o = 16; o > 0; o >>= 1) {
            sum += __shfl_xor_sync(0xffffffffu, sum, o);
            sq  += __shfl_xor_sync(0xffffffffu, sq,  o);
        }
        float mean = sum * (1.0f/128.0f);
        float var  = sq  * (1.0f/128.0f) - mean * mean;
        float r = rsqrtf(var + 1e-5f);
        float o0 = (v0 - mean) * r * sc4.x + bc4.x;
        float o1 = (v1 - mean) * r * sc4.y + bc4.y;
        float o2 = (v2 - mean) * r * sc4.z + bc4.z;
        float o3 = (v3 - mean) * r * sc4.w + bc4.w;
        __half2* d = (__half2*)(smc + (lane >> 3) * CHB + row * SMSB + (lane & 7) * 8);
        d[0] = __floats2half2_rn(o0, o1);
        d[1] = __floats2half2_rn(o2, o3);
    }
}

// ---------------- feature build + grid index + counts (fp16 output) ----------------
__global__ void feat_kernel(const float* __restrict__ x) {
    int i = blockIdx.x * blockDim.x + threadIdx.x;
    if (i >= NP) return;
    const float* xr = x + (size_t)i * 24;
    float lat = xr[0];
    if (lat == -90.0f) lat += 0.0001f;
    float lon = xr[1];
    float t   = xr[2];

    int lati = (int)floorf(90.0f - lat);
    int loni = (int)fmodf(180.0f + floorf(lon + 180.0f), 360.0f);
    int cell = lati * GW + loni;
    g_flat[i] = cell;
    atomicAdd(&g_cnt[cell], 1.0f);

    __half* f = g_feat + (size_t)i * 96;
    f[0] = __float2half_rn(lat * (1.0f/90.0f));
    f[1] = __float2half_rn(lon * (1.0f/180.0f));
    f[2] = __float2half_rn(t   * (1.0f/12.0f));
    #pragma unroll
    for (int j = 3; j < 24; j++) f[j] = __float2half_rn(xr[j]);

    float p0 = -lat - floorf(-lat);
    float p1 =  lon - floorf(lon);
    float p2 =  t + 1.0f;
    f[24] = __float2half_rn(p0); f[25] = __float2half_rn(p1); f[26] = __float2half_rn(p2);
    float p[3] = {p0, p1, p2};
    #pragma unroll
    for (int c = 0; c < 3; c++) {
        float fr = 3.14159274101257324f;
        #pragma unroll
        for (int k = 0; k < 8; k++) {
            float ang = p[c] * fr;
            f[27 + c*8 + k] = __float2half_rn(sinf(ang));
            f[51 + c*8 + k] = __float2half_rn(cosf(ang));
            fr *= 2.0f;
        }
    }
    #pragma unroll
    for (int j = 75; j < 96; j++) f[j] = __float2half_rn(0.0f);
}

// ---------------- all-in-one weight transpose + fp16 round ----------------
__global__ void wconv(const float* __restrict__ W_emb, const float* __restrict__ Wqkv,
                      const float* __restrict__ Wo, const float* __restrict__ Wf1,
                      const float* __restrict__ Wf2, const float* __restrict__ W_comb) {
    int idx = blockIdx.x * blockDim.x + threadIdx.x;
    if (idx >= 704512) return;
    const float* srcs[6] = {W_emb, Wqkv, Wo, Wf1, Wf2, W_comb};
    const int sel [10] = {0,1,1,2,2,3,3,4,4,5};
    const int soff[10] = {0,0,49152,0,16384,0,65536,0,65536,0};
    const int Kt  [10] = {75,128,128,128,128,128,128,512,512,512};
    const int Nt  [10] = {512,384,384,128,128,512,512,128,128,512};
    const int Kp  [10] = {96,128,128,128,128,128,128,512,512,512};
    const int dst [10] = {0,49152,98304,147456,163840,180224,245760,311296,376832,442368};
    int m = 0;
    #pragma unroll
    for (int i = 1; i < 10; i++) if (idx >= dst[i]) m = i;
    int local = idx - dst[m];
    int n = local / Kp[m];
    int k = local - n * Kp[m];
    float v = (k < Kt[m]) ? srcs[sel[m]][soff[m] + (size_t)k * Nt[m] + n] : 0.0f;
    g_wt[idx] = __float2half_rn(v);
}

// ---------------- generic fp16 GEMM, R12 scheme: ring-4, depth-2, 1 sync/chunk ----------------
template<int EPI, bool OUT16>
__global__ void __launch_bounds__(256, 2)
gemm_tc16(const __half* __restrict__ A, const __half* __restrict__ Bt,
          const float* __restrict__ bias, const void* __restrict__ R,
          void* __restrict__ C, int M, int N, int K, int lda, int ldb) {
    extern __shared__ char smc[];
    const int tid  = threadIdx.x;
    const int lane = tid & 31;
    const int w    = tid >> 5;
    const int wm   = w & 3;
    const int wn   = w >> 2;
    const int bm   = blockIdx.y * 128;
    const int bn   = blockIdx.x * 128;

    const uint32_t sA = (uint32_t)__cvta_generic_to_shared(smc);
    const uint32_t sB = sA + 4*CHB;

    float acc[2][8][4];
    #pragma unroll
    for (int mi = 0; mi < 2; mi++)
        #pragma unroll
        for (int ni = 0; ni < 8; ni++)
            #pragma unroll
            for (int r = 0; r < 4; r++) acc[mi][ni][r] = 0.0f;

    const int lrow = (lane & 7) + ((lane >> 3) & 1) * 8;
    const int lk2  = ((lane >> 4) & 1) * 8;
    const int ra0  = wm * 32 + lrow;
    const int rb0  = wn * 64 + lrow;
    const int nc   = K >> 5;

    auto load_chunk = [&](int c) {
        int buf = c & 3;
        int k0  = c * 32;
        #pragma unroll
        for (int l = 0; l < 2; l++) {
            int idx = tid + l * 256;      // 0..511
            int row = idx >> 2;
            int g   = idx & 3;
            bool pa = (bm + row) < M;
            const void* src = pa ? (const void*)(A + (size_t)(bm + row) * lda + k0 + g * 8)
                                 : (const void*)A;
            cpasync16(sA + (uint32_t)(buf*CHB + row*SMSB + g*16), src, pa);
        }
        #pragma unroll
        for (int l = 0; l < 2; l++) {
            int idx = tid + l * 256;
            int row = idx >> 2;
            int g   = idx & 3;
            cpasync16(sB + (uint32_t)(buf*CHB + row*SMSB + g*16),
                      Bt + (size_t)(bn + row) * ldb + k0 + g * 8, true);
        }
        cp_commit();
    };

    load_chunk(0);
    if (nc > 1) load_chunk(1);
    for (int c = 0; c < nc; c++) {
        if (c + 2 < nc) {
            load_chunk(c + 2);
            asm volatile("cp.async.wait_group 2;\n" ::);
        } else if (c + 1 < nc) {
            asm volatile("cp.async.wait_group 1;\n" ::);
        } else {
            asm volatile("cp.async.wait_group 0;\n" ::);
        }
        __syncthreads();                          // publish chunk c + fence ring reuse
        int buf = c & 3;
        mma_tile16(sA + (uint32_t)(buf*CHB), sB + (uint32_t)(buf*CHB), ra0, rb0, lk2, acc);
    }
    epi12816<EPI, OUT16>(acc, bias, R, C, M, N, bm, bn, wm, wn, lane);
}

// ---------------- full transformer layer in one kernel ----------------
// smem chunks (20 x CHB = 200KB):
//   [0-3]  A    : LN'd tile / attn-out
//   [4-15] R1   : qkv (q 4-7, k 8-11, v 12-15) -> later Hnew 4-7, G 8-11, B2 12-15
//   [16-19] W   : Bq ring -> Wo -> B1
__global__ void __launch_bounds__(256, 1)
layer16(__half* __restrict__ H, const __half* __restrict__ Bq,
        const __half* __restrict__ Bo, const __half* __restrict__ B1t,
        const __half* __restrict__ B2t,
        const float* __restrict__ bqkv, const float* __restrict__ bo,
        const float* __restrict__ bf1, const float* __restrict__ bf2,
        const float* __restrict__ ln1s, const float* __restrict__ ln1b,
        const float* __restrict__ ln2s, const float* __restrict__ ln2b, int M) {
    extern __shared__ char smc[];
    const int tid  = threadIdx.x;
    const int lane = tid & 31;
    const int w    = tid >> 5;
    const int wm   = w & 3;
    const int wn   = w >> 2;
    const int bm   = blockIdx.y * 128;

    const uint32_t sA  = (uint32_t)__cvta_generic_to_shared(smc);
    const uint32_t sW  = sA + 16*CHB;
    const uint32_t sG  = sA + 8*CHB;
    const uint32_t sB2 = sA + 12*CHB;
    char* smq = smc + 4*CHB;

    const int lrow = (lane & 7) + ((lane >> 3) & 1) * 8;
    const int lk2  = ((lane >> 4) & 1) * 8;
    const int ra0  = wm * 32 + lrow;
    const int rb0  = wn * 64 + lrow;

    // qkv weight chunk s (= nb*4 + kc) into W ring buf s&3
    auto loadBq = [&](int s) {
        int nb = s >> 2, kc = s & 3, buf = s & 3;
        #pragma unroll
        for (int l = 0; l < 2; l++) {
            int idx = tid + l * 256;
            int row = idx >> 2;
            int g   = idx & 3;
            cpasync16(sW + (uint32_t)(buf*CHB + row*SMSB + g*16),
                      Bq + (size_t)(nb * 128 + row) * 128 + kc * 32 + g * 8, true);
        }
        cp_commit();
    };
    auto loadB1 = [&](int nb) {
        #pragma unroll
        for (int kc = 0; kc < 4; kc++) {
            #pragma unroll
            for (int l = 0; l < 2; l++) {
                int idx = tid + l * 256;
                int row = idx >> 2;
                int g   = idx & 3;
                cpasync16(sW + (uint32_t)(kc*CHB + row*SMSB + g*16),
                          B1t + (size_t)(nb * 128 + row) * 128 + kc * 32 + g * 8, true);
            }
        }
        cp_commit();
    };
    auto loadB2 = [&](int nb) {
        #pragma unroll
        for (int kc = 0; kc < 4; kc++) {
            #pragma unroll
            for (int l = 0; l < 2; l++) {
                int idx = tid + l * 256;
                int row = idx >> 2;
                int g   = idx & 3;
                cpasync16(sB2 + (uint32_t)(kc*CHB + row*SMSB + g*16),
                          B2t + (size_t)row * 512 + nb * 128 + kc * 32 + g * 8, true);
            }
        }
        cp_commit();
    };

    // ---- phase 1: LN1 + QKV ----
    loadBq(0);
    loadBq(1);
    ln_to_smem(H, smc, ln1s, ln1b, bm, M, w, lane);

    {
        float acc[2][8][4];
        for (int s = 0; s < 12; s++) {
            if (s + 2 < 12) {
                loadBq(s + 2);
                asm volatile("cp.async.wait_group 2;\n" ::);
            } else if (s + 1 < 12) {
                asm volatile("cp.async.wait_group 1;\n" ::);
            } else {
                asm volatile("cp.async.wait_group 0;\n" ::);
            }
            __syncthreads();
            if ((s & 3) == 0) {
                #pragma unroll
                for (int mi = 0; mi < 2; mi++)
                    #pragma unroll
                    for (int ni = 0; ni < 8; ni++)
                        #pragma unroll
                        for (int r = 0; r < 4; r++) acc[mi][ni][r] = 0.0f;
            }
            mma_tile16(sA + (uint32_t)((s & 3)*CHB), sW + (uint32_t)((s & 3)*CHB),
                       ra0, rb0, lk2, acc);
            if ((s & 3) == 3) {
                int nb = s >> 2;
                const int r0 = wm * 32 + (lane >> 2);
                const int c0 = wn * 64 + (lane & 3) * 2;
                #pragma unroll
                for (int mi = 0; mi < 2; mi++) {
                    #pragma unroll
                    for (int half = 0; half < 2; half++) {
                        int row = r0 + mi * 16 + half * 8;
                        #pragma unroll
                        for (int ni = 0; ni < 8; ni++) {
                            int col = c0 + ni * 8;
                            int gcol = nb * 128 + col;
                            float v0 = acc[mi][ni][half*2 + 0] + bqkv[gcol];
                            float v1 = acc[mi][ni][half*2 + 1] + bqkv[gcol + 1];
                            *(__half2*)(smq + (gcol >> 5) * CHB + row * SMSB + (gcol & 31) * 2)
                                = __floats2half2_rn(v0, v1);
                        }
                    }
                }
            }
        }
    }

    __syncthreads();   // qkv in smem published; W ring reads done

    // ---- phase 2: attention (Wo prefetch overlapped) ----
    #pragma unroll
    for (int kc = 0; kc < 4; kc++) {
        #pragma unroll
        for (int l = 0; l < 2; l++) {
            int idx = tid + l * 256;
            int row = idx >> 2;
            int g   = idx & 3;
            cpasync16(sW + (uint32_t)(kc*CHB + row*SMSB + g*16),
                      Bo + (size_t)row * 128 + kc * 32 + g * 8, true);
        }
    }
    cp_commit();

    {
        int p_local = tid >> 3;
        int hh = tid & 7;
        int p = (bm >> 2) + p_local;
        int hc   = hh >> 1;
        int hoff = (hh & 1) * 32;
        if (p < NP) {
            uint4 K0[4], K1[4], V0[4], V1[4];
            #pragma unroll
            for (int ki = 0; ki < 4; ki++) {
                const char* rk = smq + (4 + hc) * CHB + (p_local * 4 + ki) * SMSB + hoff;
                const char* rv = smq + (8 + hc) * CHB + (p_local * 4 + ki) * SMSB + hoff;
                K0[ki] = *(const uint4*)rk;
                K1[ki] = *(const uint4*)(rk + 16);
                V0[ki] = *(const uint4*)rv;
                V1[ki] = *(const uint4*)(rv + 16);
            }
            #pragma unroll
            for (int qi = 0; qi < 4; qi++) {
                int row = p_local * 4 + qi;
                const char* rq = smq + hc * CHB + row * SMSB + hoff;
                uint4 Q0 = *(const uint4*)rq;
                uint4 Q1 = *(const uint4*)(rq + 16);
                float q[16];
                unp16(Q0, Q1, q);
                float sc[4];
                float mx = -1e30f;
                #pragma unroll
                for (int ki = 0; ki < 4; ki++) {
                    float s = dotp(q, K0[ki], K1[ki]) * 0.25f;
                    sc[ki] = s;
                    mx = fmaxf(mx, s);
                }
                float sum = 0.0f;
                #pragma unroll
                for (int ki = 0; ki < 4; ki++) { sc[ki] = expf(sc[ki] - mx); sum += sc[ki]; }
                float inv = 1.0f / sum;
                float acco[16];
                #pragma unroll
                for (int d = 0; d < 16; d++) acco[d] = 0.0f;
                #pragma unroll
                for (int ki = 0; ki < 4; ki++)
                    accp(acco, V0[ki], V1[ki], sc[ki] * inv);
                __half2* d = (__half2*)(smc + hc * CHB + row * SMSB + hoff);
                #pragma unroll
                for (int c = 0; c < 8; c++)
                    d[c] = __floats2half2_rn(acco[2*c], acco[2*c+1]);
            }
        } else {
            #pragma unroll
            for (int qi = 0; qi < 4; qi++) {
                int row = p_local * 4 + qi;
                __half2* d = (__half2*)(smc + hc * CHB + row * SMSB + hoff);
                #pragma unroll
                for (int c = 0; c < 8; c++) d[c] = __floats2half2_rn(0.0f, 0.0f);
            }
        }
    }

    asm volatile("cp.async.wait_group 0;\n" ::);   // Wo resident
    __syncthreads();                               // publish attn-out + Wo

    // ---- phase 3: o-proj; h' = attn@Wo + bo + h(gmem) -> Hnew smem (ch 4-7) ----
    {
        float acc[2][8][4];
        #pragma unroll
        for (int mi = 0; mi < 2; mi++)
            #pragma unroll
            for (int ni = 0; ni < 8; ni++)
                #pragma unroll
                for (int r = 0; r < 4; r++) acc[mi][ni][r] = 0.0f;
        #pragma unroll
        for (int kc = 0; kc < 4; kc++)
            mma_tile16(sA + (uint32_t)(kc*CHB), sW + (uint32_t)(kc*CHB),
                       ra0, rb0, lk2, acc);
        const int r0 = wm * 32 + (lane >> 2);
        const int c0 = wn * 64 + (lane & 3) * 2;
        #pragma unroll
        for (int mi = 0; mi < 2; mi++) {
            #pragma unroll
            for (int half = 0; half < 2; half++) {
                int row = r0 + mi * 16 + half * 8;
                int gm  = bm + row;
                if (gm >= M) continue;
                #pragma unroll
                for (int ni = 0; ni < 8; ni++) {
                    int gn = c0 + ni * 8;
                    float v0 = acc[mi][ni][half*2 + 0] + bo[gn];
                    float v1 = acc[mi][ni][half*2 + 1] + bo[gn + 1];
                    __half2 rh = *(const __half2*)(H + (size_t)gm * 128 + gn);
                    float2 rf = __half22float2(rh);
                    v0 += rf.x; v1 += rf.y;
                    *(__half2*)(smq + (gn >> 5) * CHB + row * SMSB + (gn & 31) * 2)
                        = __floats2half2_rn(v0, v1);
                }
            }
        }
    }
    __syncthreads();   // Hnew published; Wo reads done; V chunks (B2 dst) dead

    // ---- phase 4: FFN weights prefetch + LN2 from smem Hnew -> A ----
    loadB1(0);
    loadB2(0);
    {
        const float4 sc4 = ((const float4*)ln2s)[lane];
        const float4 bc4 = ((const float4*)ln2b)[lane];
        #pragma unroll
        for (int rr = 0; rr < 16; rr++) {
            int row = w * 16 + rr;
            int gm  = bm + row;
            float v0 = 0.0f, v1 = 0.0f, v2 = 0.0f, v3 = 0.0f;
            if (gm < M) {
                uint2 u = *(const uint2*)(smq + (lane >> 3) * CHB + row * SMSB + (lane & 7) * 8);
                float2 fa = __half22float2(*(const __half2*)&u.x);
                float2 fb = __half22float2(*(const __half2*)&u.y);
                v0 = fa.x; v1 = fa.y; v2 = fb.x; v3 = fb.y;
            }
            float sum = v0 + v1 + v2 + v3;
            float sq  = v0*v0 + v1*v1 + v2*v2 + v3*v3;
            #pragma unroll
            for (int o = 16; o > 0; o >>= 1) {
                sum += __shfl_xor_sync(0xffffffffu, sum, o);
                sq  += __shfl_xor_sync(0xffffffffu, sq,  o);
            }
            float mean = sum * (1.0f/128.0f);
            float var  = sq  * (1.0f/128.0f) - mean * mean;
            float r = rsqrtf(var + 1e-5f);
            float o0 = (v0 - mean) * r * sc4.x + bc4.x;
            float o1 = (v1 - mean) * r * sc4.y + bc4.y;
            float o2 = (v2 - mean) * r * sc4.z + bc4.z;
            float o3 = (v3 - mean) * r * sc4.w + bc4.w;
            __half2* d = (__half2*)(smc + (lane >> 3) * CHB + row * SMSB + (lane & 7) * 8);
            d[0] = __floats2half2_rn(o0, o1);
            d[1] = __floats2half2_rn(o2, o3);
        }
    }
    asm volatile("cp.async.wait_group 0;\n" ::);
    __syncthreads();   // B1[0], B2[0], LN2 tile published

    // ---- phase 5: FFN ----
    float acc2[2][8][4];
    #pragma unroll
    for (int mi = 0; mi < 2; mi++)
        #pragma unroll
        for (int ni = 0; ni < 8; ni++)
            #pragma unroll
            for (int r = 0; r < 4; r++) acc2[mi][ni][r] = 0.0f;

    for (int nb = 0; nb < 4; nb++) {
        if (nb > 0) {
            asm volatile("cp.async.wait_group 1;\n" ::);   // B1[nb] resident (B2[nb] may fly)
            __syncthreads();                               // publish B1[nb]
        }
        // FF1: A x B1[nb]
        float acc1[2][8][4];
        #pragma unroll
        for (int mi = 0; mi < 2; mi++)
            #pragma unroll
            for (int ni = 0; ni < 8; ni++)
                #pragma unroll
                for (int r = 0; r < 4; r++) acc1[mi][ni][r] = 0.0f;
        #pragma unroll
        for (int kc = 0; kc < 4; kc++)
            mma_tile16(sA + (uint32_t)(kc*CHB), sW + (uint32_t)(kc*CHB),
                       ra0, rb0, lk2, acc1);
        // gelu + bias -> G
        {
            const int r0 = wm * 32 + (lane >> 2);
            const int c0 = wn * 64 + (lane & 3) * 2;
            #pragma unroll
            for (int mi = 0; mi < 2; mi++) {
                #pragma unroll
                for (int half = 0; half < 2; half++) {
                    int row = r0 + mi * 16 + half * 8;
                    #pragma unroll
                    for (int ni = 0; ni < 8; ni++) {
                        int col = c0 + ni * 8;
                        float v0 = gelu_t(acc1[mi][ni][half*2 + 0] + bf1[nb * 128 + col]);
                        float v1 = gelu_t(acc1[mi][ni][half*2 + 1] + bf1[nb * 128 + col + 1]);
                        *(__half2*)(smc + (8 + (col >> 5)) * CHB + row * SMSB + (col & 31) * 2)
                            = __floats2half2_rn(v0, v1);
                    }
                }
            }
        }
        asm volatile("cp.async.wait_group 0;\n" ::);   // B2[nb] resident
        __syncthreads();                               // publish G + B2[nb]; B1 reads done
        if (nb < 3) loadB1(nb + 1);
        // FF2: G x B2[nb] -> acc2
        #pragma unroll
        for (int kc = 0; kc < 4; kc++)
            mma_tile16(sG + (uint32_t)(kc*CHB), sB2 + (uint32_t)(kc*CHB),
                       ra0, rb0, lk2, acc2);
        __syncthreads();                               // FF2 done: B2 buffer + G free
        if (nb < 3) loadB2(nb + 1);
    }

    // ---- final epilogue: h_out = acc2 + bf2 + Hnew(smem) -> gmem H ----
    {
        const int r0 = wm * 32 + (lane >> 2);
        const int c0 = wn * 64 + (lane & 3) * 2;
        #pragma unroll
        for (int mi = 0; mi < 2; mi++) {
            #pragma unroll
            for (int half = 0; half < 2; half++) {
                int row = r0 + mi * 16 + half * 8;
                int gm  = bm + row;
                if (gm >= M) continue;
                #pragma unroll
                for (int ni = 0; ni < 8; ni++) {
                    int gn = c0 + ni * 8;
                    float v0 = acc2[mi][ni][half*2 + 0] + bf2[gn];
                    float v1 = acc2[mi][ni][half*2 + 1] + bf2[gn + 1];
                    __half2 rh = *(const __half2*)(smq + (gn >> 5) * CHB + row * SMSB + (gn & 31) * 2);
                    float2 rf = __half22float2(rh);
                    v0 += rf.x; v1 += rf.y;
                    *(__half2*)(H + (size_t)gm * 128 + gn) = __floats2half2_rn(v0, v1);
                }
            }
        }
    }
}

// ---------------- output init + final divide (vectorized) ----------------
__global__ void zero_kernel(float4* __restrict__ out) {
    int i = blockIdx.x * blockDim.x + threadIdx.x;
    int n4 = NCELL * CLN / 4;
    if (i < n4) out[i] = make_float4(0.f, 0.f, 0.f, 0.f);
    else if (i < n4 + NCELL) g_cnt[i - n4] = 0.0f;
}

__global__ void div_kernel(float4* __restrict__ out) {
    int i = blockIdx.x * blockDim.x + threadIdx.x;
    if (i >= NCELL * CLN / 4) return;
    float inv = 1.0f / fmaxf(g_cnt[i >> 7], 1.0f);
    float4 v = out[i];
    v.x *= inv; v.y *= inv; v.z *= inv; v.w *= inv;
    out[i] = v;
}

// ---------------- driver ----------------
extern "C" void kernel_launch(void* const* d_in, const int* in_sizes, int n_in,
                              void* d_out, int out_size) {
    const float* x      = (const float*)d_in[0];
    const float* W_emb  = (const float*)d_in[1];
    const float* b_emb  = (const float*)d_in[2];
    const float* ln1_s  = (const float*)d_in[3];
    const float* ln1_b  = (const float*)d_in[4];
    const float* Wqkv   = (const float*)d_in[5];
    const float* bqkv   = (const float*)d_in[6];
    const float* Wo     = (const float*)d_in[7];
    const float* bo     = (const float*)d_in[8];
    const float* ln2_s  = (const float*)d_in[9];
    const float* ln2_b  = (const float*)d_in[10];
    const float* Wf1    = (const float*)d_in[11];
    const float* bf1    = (const float*)d_in[12];
    const float* Wf2    = (const float*)d_in[13];
    const float* bf2    = (const float*)d_in[14];
    const float* W_comb = (const float*)d_in[15];
    const float* b_comb = (const float*)d_in[16];
    float* out = (float*)d_out;

    __half *p_feat, *p_h, *p_wt;
    cudaGetSymbolAddress((void**)&p_feat, g_feat);
    cudaGetSymbolAddress((void**)&p_h,    g_h);
    cudaGetSymbolAddress((void**)&p_wt,   g_wt);

    const int SMEM   = 8 * CHB;    // 81920
    const int SMEM_F = 20 * CHB;   // 204800
    static bool attr_done = false;
    if (!attr_done) {
        cudaFuncSetAttribute((const void*)gemm_tc16<0,true>,  cudaFuncAttributeMaxDynamicSharedMemorySize, SMEM);
        cudaFuncSetAttribute((const void*)gemm_tc16<3,false>, cudaFuncAttributeMaxDynamicSharedMemorySize, SMEM);
        cudaFuncSetAttribute((const void*)layer16, cudaFuncAttributeMaxDynamicSharedMemorySize, SMEM_F);
        attr_done = true;
    }

    const int TB = 256;

    // fp16 weight offsets in g_wt
    __half* wembT  = p_wt + 0;        // [512][96]
    __half* wqkvT0 = p_wt + 49152;    // [384][128]
    __half* wqkvT1 = p_wt + 98304;
    __half* woT0   = p_wt + 147456;   // [128][128]
    __half* woT1   = p_wt + 163840;
    __half* wf1T0  = p_wt + 180224;   // [512][128]
    __half* wf1T1  = p_wt + 245760;
    __half* wf2T0  = p_wt + 311296;   // [128][512]
    __half* wf2T1  = p_wt + 376832;
    __half* wcombT = p_wt + 442368;   // [512][512]

    wconv<<<(704512 + TB - 1) / TB, TB>>>(W_emb, Wqkv, Wo, Wf1, Wf2, W_comb);
    // zero out + counts BEFORE feat (feat accumulates counts)
    zero_kernel<<<(NCELL * CLN / 4 + NCELL + TB - 1) / TB, TB>>>((float4*)out);
    feat_kernel<<<(NP + TB - 1) / TB, TB>>>(x);

    // embedding: feat(NP x 96 fp16) @ W_emb -> h (fp16)
    gemm_tc16<0,true><<<dim3(4, (NP + 127) / 128), TB, SMEM>>>(
        p_feat, wembT, b_emb, nullptr, p_h, NP, 512, 96, 96, 96);

    const __half* wqkvT[2] = {wqkvT0, wqkvT1};
    const __half* woT[2]   = {woT0, woT1};
    const __half* wf1T[2]  = {wf1T0, wf1T1};
    const __half* wf2T[2]  = {wf2T0, wf2T1};
    const int MB = (NTOK + 127) / 128;   // 2048

    for (int i = 0; i < 2; i++) {
        // full transformer layer, one kernel
        layer16<<<dim3(1, MB), TB, SMEM_F>>>(p_h, wqkvT[i], woT[i], wf1T[i], wf2T[i],
                                             bqkv + i * 384, bo + i * 128,
                                             bf1 + i * 512, bf2 + i * 128,
                                             ln1_s + i * 128, ln1_b + i * 128,
                                             ln2_s + i * 128, ln2_b + i * 128, NTOK);
    }

    // head: h(NP x 512 fp16) @ W_comb -> scattered directly into out (atomicAdd)
    gemm_tc16<3,false><<<dim3(4, (NP + 127) / 128), TB, SMEM>>>(
        p_h, wcombT, b_comb, nullptr, out, NP, 512, 512, 512, 512);

    // final divide by counts
    div_kernel<<<(NCELL * CLN / 4 + TB - 1) / TB, TB>>>((float4*)out);
}